// round 1
// baseline (speedup 1.0000x reference)
#include <cuda_runtime.h>
#include <math.h>

#define Bc 4
#define Lc 4096
#define Hc 16
#define Dc 128
#define BHc 64
#define SPLITQ 8
#define SPLITKV 8
#define EPSc 1e-6f

// ---------------- device scratch (static; no allocation allowed) ----------------
__device__ float g_qpart[BHc * SPLITQ * Dc];          // partial Q sums
__device__ float g_qglobal[BHc * Dc];                 // q_global [bh][d]
__device__ float g_alpha[BHc * Lc];                   // scores -> alpha (in place)
__device__ float g_kvpart[SPLITKV * BHc * Dc * Dc];   // 32 MB partial KV
__device__ float g_kv[BHc * Dc * Dc];                 // KV [bh][d][e]
__device__ float g_ksumpart[SPLITKV * BHc * Dc];
__device__ float g_ksum[BHc * Dc];

// ---------------- K1: partial sum of Q over L (split into SPLITQ chunks) ----------------
__global__ void k1_qpart(const float* __restrict__ Q) {
    int bh = blockIdx.x, s = blockIdx.y, d = threadIdx.x;   // blockDim = 128
    int b = bh >> 4, h = bh & 15;
    int l0 = s * (Lc / SPLITQ);
    const float* p = Q + ((b * Lc + l0) * Hc + h) * Dc + d;
    float acc = 0.f;
#pragma unroll 8
    for (int i = 0; i < Lc / SPLITQ; i++) {
        acc += *p;
        p += Hc * Dc;
    }
    g_qpart[(bh * SPLITQ + s) * Dc + d] = acc;
}

// ---------------- K1b: reduce partials -> q_global, apply mean + 1/sqrt(EMBED) ----------------
__global__ void k1b_qglobal() {
    int idx = blockIdx.x * blockDim.x + threadIdx.x;   // BHc*Dc = 8192
    if (idx >= BHc * Dc) return;
    int bh = idx / Dc, d = idx % Dc;
    float acc = 0.f;
#pragma unroll
    for (int s = 0; s < SPLITQ; s++) acc += g_qpart[(bh * SPLITQ + s) * Dc + d];
    const float scale = 1.0f / ((float)Lc * sqrtf(2048.0f));
    g_qglobal[bh * Dc + d] = acc * scale;
}

// ---------------- K2: scores[bh][l] = q_global[bh] . K[b,l,h,:] ----------------
__global__ void k2_scores(const float* __restrict__ K) {
    int bh = blockIdx.x;
    int b = bh >> 4, h = bh & 15;
    int warp = threadIdx.x >> 5, lane = threadIdx.x & 31;   // blockDim = 256
    float4 q = *(const float4*)&g_qglobal[bh * Dc + lane * 4];
    int l0 = blockIdx.y * 256 + warp * 32;
#pragma unroll 4
    for (int i = 0; i < 32; i++) {
        int l = l0 + i;
        const float4 kk = *(const float4*)(K + ((b * Lc + l) * Hc + h) * Dc + lane * 4);
        float p = q.x * kk.x + q.y * kk.y + q.z * kk.z + q.w * kk.w;
        p += __shfl_xor_sync(0xFFFFFFFFu, p, 16);
        p += __shfl_xor_sync(0xFFFFFFFFu, p, 8);
        p += __shfl_xor_sync(0xFFFFFFFFu, p, 4);
        p += __shfl_xor_sync(0xFFFFFFFFu, p, 2);
        p += __shfl_xor_sync(0xFFFFFFFFu, p, 1);
        if (lane == 0) g_alpha[bh * Lc + l] = p;
    }
}

// ---------------- K3: in-place softmax over L per (b,h), scaled by L ----------------
__global__ void k3_softmax() {
    int bh = blockIdx.x, t = threadIdx.x;   // blockDim = 256
    __shared__ float red[256];
    float v[Lc / 256];
#pragma unroll
    for (int i = 0; i < Lc / 256; i++) v[i] = g_alpha[bh * Lc + t + i * 256];

    float m = -1e30f;
#pragma unroll
    for (int i = 0; i < Lc / 256; i++) m = fmaxf(m, v[i]);
    red[t] = m;
    __syncthreads();
    for (int s = 128; s > 0; s >>= 1) {
        if (t < s) red[t] = fmaxf(red[t], red[t + s]);
        __syncthreads();
    }
    m = red[0];
    __syncthreads();

    float sum = 0.f;
#pragma unroll
    for (int i = 0; i < Lc / 256; i++) {
        v[i] = expf(v[i] - m);
        sum += v[i];
    }
    red[t] = sum;
    __syncthreads();
    for (int s = 128; s > 0; s >>= 1) {
        if (t < s) red[t] += red[t + s];
        __syncthreads();
    }
    float scale = (float)Lc / red[0];
#pragma unroll
    for (int i = 0; i < Lc / 256; i++) g_alpha[bh * Lc + t + i * 256] = v[i] * scale;
}

// ---------------- K4: partial KV[bh][d][e] += (alpha*phiK)[l][d] * V[l][e]; also partial Ksum ----------------
__global__ void __launch_bounds__(256) k4_kv(const float* __restrict__ phiK,
                                             const float* __restrict__ V) {
    int bh = blockIdx.x, s = blockIdx.y;
    int b = bh >> 4, h = bh & 15;
    __shared__ float Ks[8][Dc];
    __shared__ float Vs[8][Dc];
    int t = threadIdx.x;
    int tx = t & 15, ty = t >> 4;
    int warp = t >> 5, lane = t & 31;

    float acc[8][8];
#pragma unroll
    for (int i = 0; i < 8; i++)
#pragma unroll
        for (int j = 0; j < 8; j++) acc[i][j] = 0.f;
    float ksum[8];
#pragma unroll
    for (int i = 0; i < 8; i++) ksum[i] = 0.f;

    int l0 = s * (Lc / SPLITKV);
    for (int chunk = 0; chunk < Lc / SPLITKV; chunk += 8) {
        int l = l0 + chunk + warp;                 // one warp loads one l row
        int off = ((b * Lc + l) * Hc + h) * Dc + lane * 4;
        float a = g_alpha[bh * Lc + l];
        float4 kk = *(const float4*)(phiK + off);
        float4 vv = *(const float4*)(V + off);
        __syncthreads();   // previous chunk fully consumed
        *(float4*)&Ks[warp][lane * 4] = make_float4(kk.x * a, kk.y * a, kk.z * a, kk.w * a);
        *(float4*)&Vs[warp][lane * 4] = vv;
        __syncthreads();
#pragma unroll
        for (int ll = 0; ll < 8; ll++) {
            float af[8], bf[8];
            *(float4*)(af)     = *(const float4*)&Ks[ll][ty * 8];
            *(float4*)(af + 4) = *(const float4*)&Ks[ll][ty * 8 + 4];
            *(float4*)(bf)     = *(const float4*)&Vs[ll][tx * 8];
            *(float4*)(bf + 4) = *(const float4*)&Vs[ll][tx * 8 + 4];
            if (tx == 0) {
#pragma unroll
                for (int i = 0; i < 8; i++) ksum[i] += af[i];
            }
#pragma unroll
            for (int i = 0; i < 8; i++)
#pragma unroll
                for (int j = 0; j < 8; j++) acc[i][j] = fmaf(af[i], bf[j], acc[i][j]);
        }
    }

#pragma unroll
    for (int i = 0; i < 8; i++) {
        int d = ty * 8 + i;
        float* dst = &g_kvpart[((s * BHc + bh) * Dc + d) * Dc + tx * 8];
        *(float4*)(dst)     = make_float4(acc[i][0], acc[i][1], acc[i][2], acc[i][3]);
        *(float4*)(dst + 4) = make_float4(acc[i][4], acc[i][5], acc[i][6], acc[i][7]);
    }
    if (tx == 0) {
#pragma unroll
        for (int i = 0; i < 8; i++)
            g_ksumpart[(s * BHc + bh) * Dc + ty * 8 + i] = ksum[i];
    }
}

// ---------------- K4b: reduce KV partials ----------------
__global__ void k4b_reduce() {
    int idx = blockIdx.x * blockDim.x + threadIdx.x;   // BHc*Dc*Dc = 1M
    if (idx >= BHc * Dc * Dc) return;
    float acc = 0.f;
#pragma unroll
    for (int s = 0; s < SPLITKV; s++) acc += g_kvpart[s * (BHc * Dc * Dc) + idx];
    g_kv[idx] = acc;
}

// ---------------- K4c: reduce Ksum partials ----------------
__global__ void k4c_ksum() {
    int idx = blockIdx.x * blockDim.x + threadIdx.x;   // BHc*Dc = 8192
    if (idx >= BHc * Dc) return;
    float acc = 0.f;
#pragma unroll
    for (int s = 0; s < SPLITKV; s++) acc += g_ksumpart[s * (BHc * Dc) + idx];
    g_ksum[idx] = acc;
}

// ---------------- K5: out = (phiQ @ KV) / (phiQ . Ksum + eps) ----------------
__global__ void __launch_bounds__(256) k5_out(const float* __restrict__ phiQ,
                                              float* __restrict__ out) {
    int bh = blockIdx.x;
    int b = bh >> 4, h = bh & 15;
    int l0 = blockIdx.y * 64;
    __shared__ float As[64][32];
    __shared__ float KVs[32][Dc];
    __shared__ float Ksums[Dc];
    int t = threadIdx.x;
    int tx = t & 15, ty = t >> 4;

    if (t < Dc) Ksums[t] = g_ksum[bh * Dc + t];

    float acc[4][8];
#pragma unroll
    for (int i = 0; i < 4; i++)
#pragma unroll
        for (int j = 0; j < 8; j++) acc[i][j] = 0.f;
    float den[4] = {0.f, 0.f, 0.f, 0.f};

    for (int d0 = 0; d0 < Dc; d0 += 32) {
        __syncthreads();   // previous chunk consumed (also orders Ksums at d0=0)
        {
            int r = t >> 2, q = t & 3;   // 64 rows x 32 cols of phiQ
            const float* src = phiQ + ((b * Lc + l0 + r) * Hc + h) * Dc + d0;
            *(float4*)&As[r][q * 4]      = *(const float4*)(src + q * 4);
            *(float4*)&As[r][q * 4 + 16] = *(const float4*)(src + q * 4 + 16);
        }
        {
            int r = t >> 3, c = t & 7;   // 32 rows x 128 cols of KV
            const float* src = g_kv + (bh * Dc + d0 + r) * Dc;
#pragma unroll
            for (int k2 = 0; k2 < 4; k2++)
                *(float4*)&KVs[r][(c + 8 * k2) * 4] = *(const float4*)(src + (c + 8 * k2) * 4);
        }
        __syncthreads();
#pragma unroll
        for (int d = 0; d < 32; d++) {
            float af[4], bf[8];
#pragma unroll
            for (int i = 0; i < 4; i++) af[i] = As[ty * 4 + i][d];
            *(float4*)(bf)     = *(const float4*)&KVs[d][tx * 8];
            *(float4*)(bf + 4) = *(const float4*)&KVs[d][tx * 8 + 4];
            float ks = Ksums[d0 + d];
#pragma unroll
            for (int i = 0; i < 4; i++) den[i] = fmaf(af[i], ks, den[i]);
#pragma unroll
            for (int i = 0; i < 4; i++)
#pragma unroll
                for (int j = 0; j < 8; j++) acc[i][j] = fmaf(af[i], bf[j], acc[i][j]);
        }
    }

#pragma unroll
    for (int i = 0; i < 4; i++) {
        float inv = 1.0f / (den[i] + EPSc);
        int l = l0 + ty * 4 + i;
        float* dst = out + ((b * Lc + l) * Hc + h) * Dc + tx * 8;
        *(float4*)(dst)     = make_float4(acc[i][0] * inv, acc[i][1] * inv,
                                          acc[i][2] * inv, acc[i][3] * inv);
        *(float4*)(dst + 4) = make_float4(acc[i][4] * inv, acc[i][5] * inv,
                                          acc[i][6] * inv, acc[i][7] * inv);
    }
}

// ---------------- launcher ----------------
extern "C" void kernel_launch(void* const* d_in, const int* in_sizes, int n_in,
                              void* d_out, int out_size) {
    const float* Q    = (const float*)d_in[0];
    const float* K    = (const float*)d_in[1];
    const float* V    = (const float*)d_in[2];
    const float* phiQ = (const float*)d_in[3];
    const float* phiK = (const float*)d_in[4];
    float* out = (float*)d_out;

    k1_qpart<<<dim3(BHc, SPLITQ), 128>>>(Q);
    k1b_qglobal<<<(BHc * Dc + 255) / 256, 256>>>();
    k2_scores<<<dim3(BHc, Lc / 256), 256>>>(K);
    k3_softmax<<<BHc, 256>>>();
    k4_kv<<<dim3(BHc, SPLITKV), 256>>>(phiK, V);
    k4b_reduce<<<(BHc * Dc * Dc + 255) / 256, 256>>>();
    k4c_ksum<<<(BHc * Dc + 255) / 256, 256>>>();
    k5_out<<<dim3(BHc, Lc / 64), 256>>>(phiQ, out);
}

// round 2
// speedup vs baseline: 1.0326x; 1.0326x over previous
#include <cuda_runtime.h>
#include <math.h>

#define Bc 4
#define Lc 4096
#define Hc 16
#define Dc 128
#define BHc 64
#define SPLITQ 8
#define SPLITKV 8
#define EPSc 1e-6f

// ---------------- device scratch (static; no allocation allowed) ----------------
__device__ float g_qpart[BHc * SPLITQ * Dc];          // partial Q sums
__device__ float g_qglobal[BHc * Dc];                 // q_global [bh][d]
__device__ float g_alpha[BHc * Lc];                   // scores -> alpha (in place)
__device__ float g_kvpart[SPLITKV * BHc * Dc * Dc];   // 32 MB partial KV
__device__ float g_kv[BHc * Dc * Dc];                 // KV [bh][d][e]
__device__ float g_ksumpart[SPLITKV * BHc * Dc];
__device__ float g_ksum[BHc * Dc];

// ---------------- packed fp32x2 helpers (FFMA2 path; ptxas won't emit from C++) ----------------
__device__ __forceinline__ unsigned long long pack2(float x, float y) {
    unsigned long long r;
    asm("mov.b64 %0, {%1, %2};" : "=l"(r) : "f"(x), "f"(y));
    return r;
}
__device__ __forceinline__ void fma2(unsigned long long& d, unsigned long long a,
                                     unsigned long long b) {
    asm("fma.rn.f32x2 %0, %1, %2, %3;" : "=l"(d) : "l"(a), "l"(b), "l"(d));
}
__device__ __forceinline__ void unpack2(float& x, float& y, unsigned long long v) {
    asm("mov.b64 {%0, %1}, %2;" : "=f"(x), "=f"(y) : "l"(v));
}

// ---------------- K1: partial sum of Q over L (split into SPLITQ chunks) ----------------
__global__ void k1_qpart(const float* __restrict__ Q) {
    int bh = blockIdx.x, s = blockIdx.y, d = threadIdx.x;   // blockDim = 128
    int b = bh >> 4, h = bh & 15;
    int l0 = s * (Lc / SPLITQ);
    const float* p = Q + ((b * Lc + l0) * Hc + h) * Dc + d;
    float acc = 0.f;
#pragma unroll 8
    for (int i = 0; i < Lc / SPLITQ; i++) {
        acc += *p;
        p += Hc * Dc;
    }
    g_qpart[(bh * SPLITQ + s) * Dc + d] = acc;
}

// ---------------- K1b: reduce partials -> q_global, apply mean + 1/sqrt(EMBED) ----------------
__global__ void k1b_qglobal() {
    int idx = blockIdx.x * blockDim.x + threadIdx.x;   // BHc*Dc = 8192
    if (idx >= BHc * Dc) return;
    int bh = idx / Dc, d = idx % Dc;
    float acc = 0.f;
#pragma unroll
    for (int s = 0; s < SPLITQ; s++) acc += g_qpart[(bh * SPLITQ + s) * Dc + d];
    const float scale = 1.0f / ((float)Lc * sqrtf(2048.0f));
    g_qglobal[bh * Dc + d] = acc * scale;
}

// ---------------- K2: scores[bh][l] = q_global[bh] . K[b,l,h,:] ----------------
__global__ void k2_scores(const float* __restrict__ K) {
    int bh = blockIdx.x;
    int b = bh >> 4, h = bh & 15;
    int warp = threadIdx.x >> 5, lane = threadIdx.x & 31;   // blockDim = 256
    float4 q = *(const float4*)&g_qglobal[bh * Dc + lane * 4];
    int l0 = blockIdx.y * 256 + warp * 32;
#pragma unroll 4
    for (int i = 0; i < 32; i++) {
        int l = l0 + i;
        const float4 kk = *(const float4*)(K + ((b * Lc + l) * Hc + h) * Dc + lane * 4);
        float p = q.x * kk.x + q.y * kk.y + q.z * kk.z + q.w * kk.w;
        p += __shfl_xor_sync(0xFFFFFFFFu, p, 16);
        p += __shfl_xor_sync(0xFFFFFFFFu, p, 8);
        p += __shfl_xor_sync(0xFFFFFFFFu, p, 4);
        p += __shfl_xor_sync(0xFFFFFFFFu, p, 2);
        p += __shfl_xor_sync(0xFFFFFFFFu, p, 1);
        if (lane == 0) g_alpha[bh * Lc + l] = p;
    }
}

// ---------------- K3: in-place softmax over L per (b,h), scaled by L ----------------
__global__ void k3_softmax() {
    int bh = blockIdx.x, t = threadIdx.x;   // blockDim = 256
    __shared__ float red[256];
    float v[Lc / 256];
#pragma unroll
    for (int i = 0; i < Lc / 256; i++) v[i] = g_alpha[bh * Lc + t + i * 256];

    float m = -1e30f;
#pragma unroll
    for (int i = 0; i < Lc / 256; i++) m = fmaxf(m, v[i]);
    red[t] = m;
    __syncthreads();
    for (int s = 128; s > 0; s >>= 1) {
        if (t < s) red[t] = fmaxf(red[t], red[t + s]);
        __syncthreads();
    }
    m = red[0];
    __syncthreads();

    float sum = 0.f;
#pragma unroll
    for (int i = 0; i < Lc / 256; i++) {
        v[i] = expf(v[i] - m);
        sum += v[i];
    }
    red[t] = sum;
    __syncthreads();
    for (int s = 128; s > 0; s >>= 1) {
        if (t < s) red[t] += red[t + s];
        __syncthreads();
    }
    float scale = (float)Lc / red[0];
#pragma unroll
    for (int i = 0; i < Lc / 256; i++) g_alpha[bh * Lc + t + i * 256] = v[i] * scale;
}

// ---------------- K4: partial KV[bh][d][e] += (alpha*phiK)[l][d] * V[l][e]; also partial Ksum ----------------
__global__ void __launch_bounds__(256) k4_kv(const float* __restrict__ phiK,
                                             const float* __restrict__ V) {
    int bh = blockIdx.x, s = blockIdx.y;
    int b = bh >> 4, h = bh & 15;
    __shared__ float Ks[8][Dc];
    __shared__ float Vs[8][Dc];
    int t = threadIdx.x;
    int tx = t & 15, ty = t >> 4;
    int warp = t >> 5, lane = t & 31;

    unsigned long long acc2[8][4];
#pragma unroll
    for (int i = 0; i < 8; i++)
#pragma unroll
        for (int j = 0; j < 4; j++) acc2[i][j] = 0ULL;
    float ksum[8];
#pragma unroll
    for (int i = 0; i < 8; i++) ksum[i] = 0.f;

    int l0 = s * (Lc / SPLITKV);
    for (int chunk = 0; chunk < Lc / SPLITKV; chunk += 8) {
        int l = l0 + chunk + warp;                 // one warp loads one l row
        int off = ((b * Lc + l) * Hc + h) * Dc + lane * 4;
        float a = g_alpha[bh * Lc + l];
        float4 kk = *(const float4*)(phiK + off);
        float4 vv = *(const float4*)(V + off);
        __syncthreads();   // previous chunk fully consumed
        *(float4*)&Ks[warp][lane * 4] = make_float4(kk.x * a, kk.y * a, kk.z * a, kk.w * a);
        *(float4*)&Vs[warp][lane * 4] = vv;
        __syncthreads();
#pragma unroll
        for (int ll = 0; ll < 8; ll++) {
            float af[8];
            *(float4*)(af)     = *(const float4*)&Ks[ll][ty * 8];
            *(float4*)(af + 4) = *(const float4*)&Ks[ll][ty * 8 + 4];
            unsigned long long bf2[4];
            {
                ulonglong2 u0 = *(const ulonglong2*)&Vs[ll][tx * 8];
                ulonglong2 u1 = *(const ulonglong2*)&Vs[ll][tx * 8 + 4];
                bf2[0] = u0.x; bf2[1] = u0.y; bf2[2] = u1.x; bf2[3] = u1.y;
            }
            if (tx == 0) {
#pragma unroll
                for (int i = 0; i < 8; i++) ksum[i] += af[i];
            }
#pragma unroll
            for (int i = 0; i < 8; i++) {
                unsigned long long ap = pack2(af[i], af[i]);
#pragma unroll
                for (int j = 0; j < 4; j++) fma2(acc2[i][j], ap, bf2[j]);
            }
        }
    }

#pragma unroll
    for (int i = 0; i < 8; i++) {
        int d = ty * 8 + i;
        float r[8];
#pragma unroll
        for (int j = 0; j < 4; j++) unpack2(r[2 * j], r[2 * j + 1], acc2[i][j]);
        float* dst = &g_kvpart[((s * BHc + bh) * Dc + d) * Dc + tx * 8];
        *(float4*)(dst)     = make_float4(r[0], r[1], r[2], r[3]);
        *(float4*)(dst + 4) = make_float4(r[4], r[5], r[6], r[7]);
    }
    if (tx == 0) {
#pragma unroll
        for (int i = 0; i < 8; i++)
            g_ksumpart[(s * BHc + bh) * Dc + ty * 8 + i] = ksum[i];
    }
}

// ---------------- K4b: reduce KV partials ----------------
__global__ void k4b_reduce() {
    int idx = blockIdx.x * blockDim.x + threadIdx.x;   // BHc*Dc*Dc = 1M
    if (idx >= BHc * Dc * Dc) return;
    float acc = 0.f;
#pragma unroll
    for (int s = 0; s < SPLITKV; s++) acc += g_kvpart[s * (BHc * Dc * Dc) + idx];
    g_kv[idx] = acc;
}

// ---------------- K4c: reduce Ksum partials ----------------
__global__ void k4c_ksum() {
    int idx = blockIdx.x * blockDim.x + threadIdx.x;   // BHc*Dc = 8192
    if (idx >= BHc * Dc) return;
    float acc = 0.f;
#pragma unroll
    for (int s = 0; s < SPLITKV; s++) acc += g_ksumpart[s * (BHc * Dc) + idx];
    g_ksum[idx] = acc;
}

// ---------------- K5: out = (phiQ @ KV) / (phiQ . Ksum + eps) ----------------
__global__ void __launch_bounds__(256) k5_out(const float* __restrict__ phiQ,
                                              float* __restrict__ out) {
    int bh = blockIdx.x;
    int b = bh >> 4, h = bh & 15;
    int l0 = blockIdx.y * 64;
    __shared__ float As[64][32];
    __shared__ float KVs[32][Dc];
    __shared__ float Ksums[Dc];
    int t = threadIdx.x;
    int tx = t & 15, ty = t >> 4;

    if (t < Dc) Ksums[t] = g_ksum[bh * Dc + t];

    unsigned long long acc2[4][4];
#pragma unroll
    for (int i = 0; i < 4; i++)
#pragma unroll
        for (int j = 0; j < 4; j++) acc2[i][j] = 0ULL;
    float den[4] = {0.f, 0.f, 0.f, 0.f};

    for (int d0 = 0; d0 < Dc; d0 += 32) {
        __syncthreads();   // previous chunk consumed (also orders Ksums at d0=0)
        {
            int r = t >> 2, q = t & 3;   // 64 rows x 32 cols of phiQ
            const float* src = phiQ + ((b * Lc + l0 + r) * Hc + h) * Dc + d0;
            *(float4*)&As[r][q * 4]      = *(const float4*)(src + q * 4);
            *(float4*)&As[r][q * 4 + 16] = *(const float4*)(src + q * 4 + 16);
        }
        {
            int r = t >> 3, c = t & 7;   // 32 rows x 128 cols of KV
            const float* src = g_kv + (bh * Dc + d0 + r) * Dc;
#pragma unroll
            for (int k2 = 0; k2 < 4; k2++)
                *(float4*)&KVs[r][(c + 8 * k2) * 4] = *(const float4*)(src + (c + 8 * k2) * 4);
        }
        __syncthreads();
#pragma unroll
        for (int d = 0; d < 32; d++) {
            float af[4];
#pragma unroll
            for (int i = 0; i < 4; i++) af[i] = As[ty * 4 + i][d];
            unsigned long long bf2[4];
            {
                ulonglong2 u0 = *(const ulonglong2*)&KVs[d][tx * 8];
                ulonglong2 u1 = *(const ulonglong2*)&KVs[d][tx * 8 + 4];
                bf2[0] = u0.x; bf2[1] = u0.y; bf2[2] = u1.x; bf2[3] = u1.y;
            }
            float ks = Ksums[d0 + d];
#pragma unroll
            for (int i = 0; i < 4; i++) den[i] = fmaf(af[i], ks, den[i]);
#pragma unroll
            for (int i = 0; i < 4; i++) {
                unsigned long long ap = pack2(af[i], af[i]);
#pragma unroll
                for (int j = 0; j < 4; j++) fma2(acc2[i][j], ap, bf2[j]);
            }
        }
    }

#pragma unroll
    for (int i = 0; i < 4; i++) {
        float inv = 1.0f / (den[i] + EPSc);
        float r[8];
#pragma unroll
        for (int j = 0; j < 4; j++) unpack2(r[2 * j], r[2 * j + 1], acc2[i][j]);
        int l = l0 + ty * 4 + i;
        float* dst = out + ((b * Lc + l) * Hc + h) * Dc + tx * 8;
        *(float4*)(dst)     = make_float4(r[0] * inv, r[1] * inv, r[2] * inv, r[3] * inv);
        *(float4*)(dst + 4) = make_float4(r[4] * inv, r[5] * inv, r[6] * inv, r[7] * inv);
    }
}

// ---------------- launcher ----------------
extern "C" void kernel_launch(void* const* d_in, const int* in_sizes, int n_in,
                              void* d_out, int out_size) {
    const float* Q    = (const float*)d_in[0];
    const float* K    = (const float*)d_in[1];
    const float* V    = (const float*)d_in[2];
    const float* phiQ = (const float*)d_in[3];
    const float* phiK = (const float*)d_in[4];
    float* out = (float*)d_out;

    k1_qpart<<<dim3(BHc, SPLITQ), 128>>>(Q);
    k1b_qglobal<<<(BHc * Dc + 255) / 256, 256>>>();
    k2_scores<<<dim3(BHc, Lc / 256), 256>>>(K);
    k3_softmax<<<BHc, 256>>>();
    k4_kv<<<dim3(BHc, SPLITKV), 256>>>(phiK, V);
    k4b_reduce<<<(BHc * Dc * Dc + 255) / 256, 256>>>();
    k4c_ksum<<<(BHc * Dc + 255) / 256, 256>>>();
    k5_out<<<dim3(BHc, Lc / 64), 256>>>(phiQ, out);
}

// round 4
// speedup vs baseline: 1.9193x; 1.8588x over previous
#include <cuda_runtime.h>
#include <cuda_bf16.h>
#include <math.h>
#include <stdint.h>

#define Bc 4
#define Lc 4096
#define Hc 16
#define Dc 128
#define BHc 64
#define SPLITQ 8
#define KVS 8
#define EPSc 1e-6f

// ---------------- device scratch ----------------
__device__ float g_qpart[BHc * SPLITQ * Dc];
__device__ float g_qglobal[BHc * Dc];
__device__ float g_alpha[BHc * Lc];
__device__ float g_kvpart[(size_t)KVS * BHc * Dc * Dc];   // 33.5 MB fp32 partials
__device__ __nv_bfloat16 g_kv_hi[BHc * Dc * Dc];
__device__ __nv_bfloat16 g_kv_lo[BHc * Dc * Dc];
__device__ float g_ksumpart[KVS * BHc * Dc];
__device__ float g_ksum[BHc * Dc];

// ---------------- helpers ----------------
__device__ __forceinline__ uint32_t smem_u32(const void* p) {
    uint32_t a;
    asm("{ .reg .u64 t; cvta.to.shared.u64 t, %1; cvt.u32.u64 %0, t; }" : "=r"(a) : "l"(p));
    return a;
}
__device__ __forceinline__ void ldsm_x4(uint32_t r[4], uint32_t addr) {
    asm volatile("ldmatrix.sync.aligned.m8n8.x4.shared.b16 {%0,%1,%2,%3}, [%4];"
                 : "=r"(r[0]), "=r"(r[1]), "=r"(r[2]), "=r"(r[3]) : "r"(addr));
}
__device__ __forceinline__ void ldsm_x4_t(uint32_t r[4], uint32_t addr) {
    asm volatile("ldmatrix.sync.aligned.m8n8.x4.trans.shared.b16 {%0,%1,%2,%3}, [%4];"
                 : "=r"(r[0]), "=r"(r[1]), "=r"(r[2]), "=r"(r[3]) : "r"(addr));
}
__device__ __forceinline__ void mma16816(float c[4], const uint32_t a[4], uint32_t b0, uint32_t b1) {
    asm volatile(
        "mma.sync.aligned.m16n8k16.row.col.f32.bf16.bf16.f32 "
        "{%0,%1,%2,%3}, {%4,%5,%6,%7}, {%8,%9}, {%0,%1,%2,%3};"
        : "+f"(c[0]), "+f"(c[1]), "+f"(c[2]), "+f"(c[3])
        : "r"(a[0]), "r"(a[1]), "r"(a[2]), "r"(a[3]), "r"(b0), "r"(b1));
}
__device__ __forceinline__ void split_bf16(float x, __nv_bfloat16& h, __nv_bfloat16& l) {
    h = __float2bfloat16(x);
    l = __float2bfloat16(x - __bfloat162float(h));
}
__device__ __forceinline__ uint32_t pack_bf16(__nv_bfloat16 a, __nv_bfloat16 b) {
    __nv_bfloat162 t;
    t.x = a; t.y = b;
    return *reinterpret_cast<uint32_t*>(&t);
}
__device__ __forceinline__ void split4(float4 v, uint2& hi, uint2& lo) {
    __nv_bfloat16 h0, l0, h1, l1, h2, l2, h3, l3;
    split_bf16(v.x, h0, l0); split_bf16(v.y, h1, l1);
    split_bf16(v.z, h2, l2); split_bf16(v.w, h3, l3);
    hi.x = pack_bf16(h0, h1); hi.y = pack_bf16(h2, h3);
    lo.x = pack_bf16(l0, l1); lo.y = pack_bf16(l2, l3);
}

// ================= K1: partial sum of Q over L =================
__global__ void k1_qpart(const float* __restrict__ Q) {
    int bh = blockIdx.x, s = blockIdx.y, d = threadIdx.x;
    int b = bh >> 4, h = bh & 15;
    int l0 = s * (Lc / SPLITQ);
    const float* p = Q + ((size_t)(b * Lc + l0) * Hc + h) * Dc + d;
    float acc = 0.f;
#pragma unroll 8
    for (int i = 0; i < Lc / SPLITQ; i++) { acc += *p; p += Hc * Dc; }
    g_qpart[(bh * SPLITQ + s) * Dc + d] = acc;
}

__global__ void k1b_qglobal() {
    int idx = blockIdx.x * blockDim.x + threadIdx.x;
    if (idx >= BHc * Dc) return;
    int bh = idx / Dc, d = idx % Dc;
    float acc = 0.f;
#pragma unroll
    for (int s = 0; s < SPLITQ; s++) acc += g_qpart[(bh * SPLITQ + s) * Dc + d];
    const float scale = 1.0f / ((float)Lc * sqrtf(2048.0f));
    g_qglobal[bh * Dc + d] = acc * scale;
}

// ================= K2: scores =================
__global__ void k2_scores(const float* __restrict__ K) {
    int bh = blockIdx.x;
    int b = bh >> 4, h = bh & 15;
    int warp = threadIdx.x >> 5, lane = threadIdx.x & 31;
    float4 q = *(const float4*)&g_qglobal[bh * Dc + lane * 4];
    int l0 = blockIdx.y * 256 + warp * 32;
#pragma unroll 4
    for (int i = 0; i < 32; i++) {
        int l = l0 + i;
        const float4 kk = *(const float4*)(K + ((size_t)(b * Lc + l) * Hc + h) * Dc + lane * 4);
        float p = q.x * kk.x + q.y * kk.y + q.z * kk.z + q.w * kk.w;
        p += __shfl_xor_sync(0xFFFFFFFFu, p, 16);
        p += __shfl_xor_sync(0xFFFFFFFFu, p, 8);
        p += __shfl_xor_sync(0xFFFFFFFFu, p, 4);
        p += __shfl_xor_sync(0xFFFFFFFFu, p, 2);
        p += __shfl_xor_sync(0xFFFFFFFFu, p, 1);
        if (lane == 0) g_alpha[bh * Lc + l] = p;
    }
}

// ================= K3: softmax * L =================
__global__ void k3_softmax() {
    int bh = blockIdx.x, t = threadIdx.x;
    __shared__ float red[256];
    float v[Lc / 256];
#pragma unroll
    for (int i = 0; i < Lc / 256; i++) v[i] = g_alpha[bh * Lc + t + i * 256];
    float m = -1e30f;
#pragma unroll
    for (int i = 0; i < Lc / 256; i++) m = fmaxf(m, v[i]);
    red[t] = m; __syncthreads();
    for (int s = 128; s > 0; s >>= 1) { if (t < s) red[t] = fmaxf(red[t], red[t + s]); __syncthreads(); }
    m = red[0]; __syncthreads();
    float sum = 0.f;
#pragma unroll
    for (int i = 0; i < Lc / 256; i++) { v[i] = expf(v[i] - m); sum += v[i]; }
    red[t] = sum; __syncthreads();
    for (int s = 128; s > 0; s >>= 1) { if (t < s) red[t] += red[t + s]; __syncthreads(); }
    float scale = (float)Lc / red[0];
#pragma unroll
    for (int i = 0; i < Lc / 256; i++) g_alpha[bh * Lc + t + i * 256] = v[i] * scale;
}

// ================= k4: KVT[e][d] = sum_l V[l][e] * (alpha*phiK)[l][d]  (warp MMA) =================
// grid (BHc, KVS), 256 threads. Each block: 512 l, full 128x128 output, + fused ksum partial.
// smem tiles: 32 l-rows x 128 cols bf16 (256B rows), XOR-swizzled 16B blocks.
#define T_KHI 0
#define T_KLO 8192
#define T_VHI 16384
#define T_VLO 24576
#define T_KS  32768
#define K4_SMEM (32768 + 4096)

__global__ void __launch_bounds__(256, 2) k4_mma(const float* __restrict__ phiK,
                                                 const float* __restrict__ V) {
    __shared__ __align__(16) char smem[K4_SMEM];
    uint32_t sb = smem_u32(smem);
    int bh = blockIdx.x, s = blockIdx.y;
    int b = bh >> 4, h = bh & 15;
    int t = threadIdx.x, lane = t & 31, w = t >> 5;

    float acc[16][4];
#pragma unroll
    for (int i = 0; i < 16; i++)
#pragma unroll
        for (int j = 0; j < 4; j++) acc[i][j] = 0.f;
    float4 ksum4 = make_float4(0.f, 0.f, 0.f, 0.f);

    const int c4 = lane;       // 16B-half column index (d0 = 4*c4)
    const int rg = w;          // row group for loads

    for (int chunk = 0; chunk < 16; chunk++) {
        int l0 = s * 512 + chunk * 32;
        __syncthreads();
        // ---- load + convert 32 l rows ----
#pragma unroll
        for (int i = 0; i < 4; i++) {
            int lr = rg + 8 * i;
            int l = l0 + lr;
            size_t off = ((size_t)(b * Lc + l) * Hc + h) * Dc + c4 * 4;
            float a = g_alpha[bh * Lc + l];
            float4 kv = *(const float4*)(phiK + off);
            kv.x *= a; kv.y *= a; kv.z *= a; kv.w *= a;
            ksum4.x += kv.x; ksum4.y += kv.y; ksum4.z += kv.z; ksum4.w += kv.w;
            float4 vv = *(const float4*)(V + off);
            uint32_t wo = lr * 256 + ((((uint32_t)(c4 >> 1)) ^ (lr & 7)) << 4) + (c4 & 1) * 8;
            uint2 hi, lo;
            split4(kv, hi, lo);
            *(uint2*)(smem + T_KHI + wo) = hi;
            *(uint2*)(smem + T_KLO + wo) = lo;
            split4(vv, hi, lo);
            *(uint2*)(smem + T_VHI + wo) = hi;
            *(uint2*)(smem + T_VLO + wo) = lo;
        }
        __syncthreads();
        // ---- MMA: m=e (V tiles, ldmatrix.trans), n=d (K tiles, ldmatrix.trans), k=l ----
        int eblk = w * 2;
        int matj = lane >> 3, rr = lane & 7;
#pragma unroll
        for (int ks = 0; ks < 2; ks++) {
            int lb = ks * 16;
            int lA = lb + (matj >> 1) * 8 + rr;
            uint32_t aoff = lA * 256 + ((((uint32_t)(eblk + (matj & 1))) ^ (lA & 7)) << 4);
            uint32_t ah[4], al[4];
            ldsm_x4_t(ah, sb + T_VHI + aoff);
            ldsm_x4_t(al, sb + T_VLO + aoff);
            int lB = lb + (matj & 1) * 8 + rr;
            uint32_t brow = lB * 256;
#pragma unroll
            for (int jp = 0; jp < 8; jp++) {
                uint32_t db = (uint32_t)(jp * 2 + (matj >> 1));
                uint32_t boff = brow + ((db ^ (lB & 7)) << 4);
                uint32_t bh4[4], bl4[4];
                ldsm_x4_t(bh4, sb + T_KHI + boff);
                ldsm_x4_t(bl4, sb + T_KLO + boff);
                mma16816(acc[jp * 2],     ah, bh4[0], bh4[1]);
                mma16816(acc[jp * 2],     ah, bl4[0], bl4[1]);
                mma16816(acc[jp * 2],     al, bh4[0], bh4[1]);
                mma16816(acc[jp * 2 + 1], ah, bh4[2], bh4[3]);
                mma16816(acc[jp * 2 + 1], ah, bl4[2], bl4[3]);
                mma16816(acc[jp * 2 + 1], al, bh4[2], bh4[3]);
            }
        }
    }

    // ---- fused ksum partial (fixed-order, deterministic) ----
    __syncthreads();
    *(float4*)(smem + T_KS + (rg * 128 + c4 * 4) * 4) = ksum4;
    __syncthreads();
    if (t < 128) {
        float sum = 0.f;
        const float* ks_s = (const float*)(smem + T_KS);
#pragma unroll
        for (int g = 0; g < 8; g++) sum += ks_s[g * 128 + t];
        g_ksumpart[(s * BHc + bh) * Dc + t] = sum;
    }

    // ---- epilogue: write fp32 partials ----
    int r0 = w * 16 + (lane >> 2);
    int cc = 2 * (lane & 3);
    float* base0 = g_kvpart + (((size_t)s * BHc + bh) * Dc + r0) * Dc + cc;
    float* base1 = base0 + 8 * Dc;
#pragma unroll
    for (int j = 0; j < 16; j++) {
        *(float2*)(base0 + j * 8) = make_float2(acc[j][0], acc[j][1]);
        *(float2*)(base1 + j * 8) = make_float2(acc[j][2], acc[j][3]);
    }
}

// ================= k4b: reduce partials + split to bf16 hi/lo =================
__global__ void k4b_reduce() {
    int idx = blockIdx.x * blockDim.x + threadIdx.x;
    if (idx >= BHc * Dc * Dc) return;
    float acc = 0.f;
#pragma unroll
    for (int s = 0; s < KVS; s++) acc += g_kvpart[(size_t)s * (BHc * Dc * Dc) + idx];
    __nv_bfloat16 h, l;
    split_bf16(acc, h, l);
    g_kv_hi[idx] = h;
    g_kv_lo[idx] = l;
}

__global__ void k_ksum_reduce() {
    int idx = blockIdx.x * blockDim.x + threadIdx.x;
    if (idx >= BHc * Dc) return;
    float acc = 0.f;
#pragma unroll
    for (int s = 0; s < KVS; s++) acc += g_ksumpart[s * (BHc * Dc) + idx];
    g_ksum[idx] = acc;
}

// ================= k5: out[l][e] = (phiQ @ KVT^T) / (phiQ . ksum + eps)  (warp MMA) =================
// grid (BHc, Lc/128), 256 threads. m=l (128), n=e (128), k=d (128).
#define Q_HI 0
#define Q_LO 32768
#define G_HI 65536
#define G_LO 98304
#define D_EN 131072
#define K5_SMEM (131072 + 512)

__global__ void __launch_bounds__(256, 1) k5_mma(const float* __restrict__ phiQ,
                                                 float* __restrict__ out) {
    extern __shared__ __align__(16) char smem[];
    uint32_t sb = smem_u32(smem);
    int bh = blockIdx.x, lt = blockIdx.y;
    int b = bh >> 4, h = bh & 15;
    int l0 = lt * 128;
    int t = threadIdx.x, lane = t & 31, w = t >> 5;
    float* den_s = (float*)(smem + D_EN);

    const int c4 = lane;
    float4 ksq = *(const float4*)(g_ksum + bh * Dc + c4 * 4);

    // ---- A fill (phiQ -> bf16 hi/lo) + denominator ----
#pragma unroll
    for (int i = 0; i < 16; i++) {
        int row = w + 8 * i;
        int l = l0 + row;
        float4 q = *(const float4*)(phiQ + ((size_t)(b * Lc + l) * Hc + h) * Dc + c4 * 4);
        float part = q.x * ksq.x + q.y * ksq.y + q.z * ksq.z + q.w * ksq.w;
        part += __shfl_xor_sync(0xFFFFFFFFu, part, 16);
        part += __shfl_xor_sync(0xFFFFFFFFu, part, 8);
        part += __shfl_xor_sync(0xFFFFFFFFu, part, 4);
        part += __shfl_xor_sync(0xFFFFFFFFu, part, 2);
        part += __shfl_xor_sync(0xFFFFFFFFu, part, 1);
        if (lane == 0) den_s[row] = part;
        uint32_t wo = row * 256 + ((((uint32_t)(c4 >> 1)) ^ (row & 7)) << 4) + (c4 & 1) * 8;
        uint2 hi, lo;
        split4(q, hi, lo);
        *(uint2*)(smem + Q_HI + wo) = hi;
        *(uint2*)(smem + Q_LO + wo) = lo;
    }
    // ---- B fill (KVT bf16 hi/lo from gmem) ----
#pragma unroll
    for (int i = 0; i < 8; i++) {
        int seg = t + i * 256;
        int e = seg >> 4, db = seg & 15;
        size_t goff = ((size_t)bh * Dc + e) * Dc + db * 8;
        uint32_t wo = e * 256 + ((((uint32_t)db) ^ (e & 7)) << 4);
        *(uint4*)(smem + G_HI + wo) = *(const uint4*)(g_kv_hi + goff);
        *(uint4*)(smem + G_LO + wo) = *(const uint4*)(g_kv_lo + goff);
    }
    __syncthreads();

    float acc[16][4];
#pragma unroll
    for (int i = 0; i < 16; i++)
#pragma unroll
        for (int j = 0; j < 4; j++) acc[i][j] = 0.f;

    int mbase = w * 16;
    int matj = lane >> 3, rr = lane & 7;
#pragma unroll
    for (int ks = 0; ks < 8; ks++) {
        int rowA = mbase + (matj & 1) * 8 + rr;
        uint32_t kbA = (uint32_t)(ks * 2 + (matj >> 1));
        uint32_t aoff = rowA * 256 + ((kbA ^ (rowA & 7)) << 4);
        uint32_t ah[4], al[4];
        ldsm_x4(ah, sb + Q_HI + aoff);
        ldsm_x4(al, sb + Q_LO + aoff);
        uint32_t kbB = (uint32_t)(ks * 2 + (matj & 1));
#pragma unroll
        for (int jp = 0; jp < 8; jp++) {
            int rowB = (jp * 2 + (matj >> 1)) * 8 + rr;
            uint32_t boff = rowB * 256 + ((kbB ^ (rowB & 7)) << 4);
            uint32_t bh4[4], bl4[4];
            ldsm_x4(bh4, sb + G_HI + boff);
            ldsm_x4(bl4, sb + G_LO + boff);
            mma16816(acc[jp * 2],     ah, bh4[0], bh4[1]);
            mma16816(acc[jp * 2],     ah, bl4[0], bl4[1]);
            mma16816(acc[jp * 2],     al, bh4[0], bh4[1]);
            mma16816(acc[jp * 2 + 1], ah, bh4[2], bh4[3]);
            mma16816(acc[jp * 2 + 1], ah, bl4[2], bl4[3]);
            mma16816(acc[jp * 2 + 1], al, bh4[2], bh4[3]);
        }
    }

    // ---- epilogue: divide by denominator, write out ----
    int r0 = mbase + (lane >> 2);
    int cc = 2 * (lane & 3);
    float i0 = 1.0f / (den_s[r0] + EPSc);
    float i1 = 1.0f / (den_s[r0 + 8] + EPSc);
    float* o0 = out + ((size_t)(b * Lc + l0 + r0) * Hc + h) * Dc + cc;
    float* o1 = out + ((size_t)(b * Lc + l0 + r0 + 8) * Hc + h) * Dc + cc;
#pragma unroll
    for (int j = 0; j < 16; j++) {
        *(float2*)(o0 + j * 8) = make_float2(acc[j][0] * i0, acc[j][1] * i0);
        *(float2*)(o1 + j * 8) = make_float2(acc[j][2] * i1, acc[j][3] * i1);
    }
}

// ================= launcher =================
extern "C" void kernel_launch(void* const* d_in, const int* in_sizes, int n_in,
                              void* d_out, int out_size) {
    const float* Q    = (const float*)d_in[0];
    const float* K    = (const float*)d_in[1];
    const float* V    = (const float*)d_in[2];
    const float* phiQ = (const float*)d_in[3];
    const float* phiK = (const float*)d_in[4];
    float* out = (float*)d_out;

    cudaFuncSetAttribute(k5_mma, cudaFuncAttributeMaxDynamicSharedMemorySize, K5_SMEM);

    k1_qpart<<<dim3(BHc, SPLITQ), 128>>>(Q);
    k1b_qglobal<<<(BHc * Dc + 255) / 256, 256>>>();
    k2_scores<<<dim3(BHc, Lc / 256), 256>>>(K);
    k3_softmax<<<BHc, 256>>>();
    k4_mma<<<dim3(BHc, KVS), 256>>>(phiK, V);
    k_ksum_reduce<<<(BHc * Dc + 255) / 256, 256>>>();
    k4b_reduce<<<(BHc * Dc * Dc + 255) / 256, 256>>>();
    k5_mma<<<dim3(BHc, Lc / 128), 256, K5_SMEM>>>(phiQ, out);
}

// round 5
// speedup vs baseline: 2.2163x; 1.1547x over previous
#include <cuda_runtime.h>
#include <cuda_bf16.h>
#include <math.h>
#include <stdint.h>

#define Bc 4
#define Lc 4096
#define Hc 16
#define Dc 128
#define BHc 64
#define SPLITQ 8
#define KVS 4
#define EPSc 1e-6f

// ---------------- device scratch ----------------
__device__ float g_qpart[BHc * SPLITQ * Dc];
__device__ float g_qglobal[BHc * Dc];
__device__ float g_alpha[BHc * Lc];
__device__ float g_kvpart[(size_t)KVS * BHc * Dc * Dc];   // 16.8 MB fp32 partials
__device__ __nv_bfloat16 g_kv_hi[BHc * Dc * Dc];
__device__ __nv_bfloat16 g_kv_lo[BHc * Dc * Dc];
__device__ float g_ksumpart[KVS * BHc * Dc];
__device__ float g_ksum[BHc * Dc];

// ---------------- helpers ----------------
__device__ __forceinline__ uint32_t smem_u32(const void* p) {
    uint32_t a;
    asm("{ .reg .u64 t; cvta.to.shared.u64 t, %1; cvt.u32.u64 %0, t; }" : "=r"(a) : "l"(p));
    return a;
}
__device__ __forceinline__ void ldsm_x4(uint32_t r[4], uint32_t addr) {
    asm volatile("ldmatrix.sync.aligned.m8n8.x4.shared.b16 {%0,%1,%2,%3}, [%4];"
                 : "=r"(r[0]), "=r"(r[1]), "=r"(r[2]), "=r"(r[3]) : "r"(addr));
}
__device__ __forceinline__ void ldsm_x4_t(uint32_t r[4], uint32_t addr) {
    asm volatile("ldmatrix.sync.aligned.m8n8.x4.trans.shared.b16 {%0,%1,%2,%3}, [%4];"
                 : "=r"(r[0]), "=r"(r[1]), "=r"(r[2]), "=r"(r[3]) : "r"(addr));
}
__device__ __forceinline__ void mma16816(float c[4], const uint32_t a[4], uint32_t b0, uint32_t b1) {
    asm volatile(
        "mma.sync.aligned.m16n8k16.row.col.f32.bf16.bf16.f32 "
        "{%0,%1,%2,%3}, {%4,%5,%6,%7}, {%8,%9}, {%0,%1,%2,%3};"
        : "+f"(c[0]), "+f"(c[1]), "+f"(c[2]), "+f"(c[3])
        : "r"(a[0]), "r"(a[1]), "r"(a[2]), "r"(a[3]), "r"(b0), "r"(b1));
}
__device__ __forceinline__ void split_bf16(float x, __nv_bfloat16& h, __nv_bfloat16& l) {
    h = __float2bfloat16(x);
    l = __float2bfloat16(x - __bfloat162float(h));
}
__device__ __forceinline__ uint32_t pack_bf16(__nv_bfloat16 a, __nv_bfloat16 b) {
    __nv_bfloat162 t;
    t.x = a; t.y = b;
    return *reinterpret_cast<uint32_t*>(&t);
}
__device__ __forceinline__ void split4(float4 v, uint2& hi, uint2& lo) {
    __nv_bfloat16 h0, l0, h1, l1, h2, l2, h3, l3;
    split_bf16(v.x, h0, l0); split_bf16(v.y, h1, l1);
    split_bf16(v.z, h2, l2); split_bf16(v.w, h3, l3);
    hi.x = pack_bf16(h0, h1); hi.y = pack_bf16(h2, h3);
    lo.x = pack_bf16(l0, l1); lo.y = pack_bf16(l2, l3);
}

// ================= K1: partial sum of Q over L =================
__global__ void k1_qpart(const float* __restrict__ Q) {
    int bh = blockIdx.x, s = blockIdx.y, d = threadIdx.x;
    int b = bh >> 4, h = bh & 15;
    int l0 = s * (Lc / SPLITQ);
    const float* p = Q + ((size_t)(b * Lc + l0) * Hc + h) * Dc + d;
    float acc = 0.f;
#pragma unroll 8
    for (int i = 0; i < Lc / SPLITQ; i++) { acc += *p; p += Hc * Dc; }
    g_qpart[(bh * SPLITQ + s) * Dc + d] = acc;
}

__global__ void k1b_qglobal() {
    int idx = blockIdx.x * blockDim.x + threadIdx.x;
    if (idx >= BHc * Dc) return;
    int bh = idx / Dc, d = idx % Dc;
    float acc = 0.f;
#pragma unroll
    for (int s = 0; s < SPLITQ; s++) acc += g_qpart[(bh * SPLITQ + s) * Dc + d];
    const float scale = 1.0f / ((float)Lc * sqrtf(2048.0f));
    g_qglobal[bh * Dc + d] = acc * scale;
}

// ================= K2: scores =================
__global__ void k2_scores(const float* __restrict__ K) {
    int bh = blockIdx.x;
    int b = bh >> 4, h = bh & 15;
    int warp = threadIdx.x >> 5, lane = threadIdx.x & 31;
    float4 q = *(const float4*)&g_qglobal[bh * Dc + lane * 4];
    int l0 = blockIdx.y * 256 + warp * 32;
#pragma unroll 4
    for (int i = 0; i < 32; i++) {
        int l = l0 + i;
        const float4 kk = *(const float4*)(K + ((size_t)(b * Lc + l) * Hc + h) * Dc + lane * 4);
        float p = q.x * kk.x + q.y * kk.y + q.z * kk.z + q.w * kk.w;
        p += __shfl_xor_sync(0xFFFFFFFFu, p, 16);
        p += __shfl_xor_sync(0xFFFFFFFFu, p, 8);
        p += __shfl_xor_sync(0xFFFFFFFFu, p, 4);
        p += __shfl_xor_sync(0xFFFFFFFFu, p, 2);
        p += __shfl_xor_sync(0xFFFFFFFFu, p, 1);
        if (lane == 0) g_alpha[bh * Lc + l] = p;
    }
}

// ================= K3: softmax * L =================
__global__ void k3_softmax() {
    int bh = blockIdx.x, t = threadIdx.x;
    __shared__ float red[256];
    float v[Lc / 256];
#pragma unroll
    for (int i = 0; i < Lc / 256; i++) v[i] = g_alpha[bh * Lc + t + i * 256];
    float m = -1e30f;
#pragma unroll
    for (int i = 0; i < Lc / 256; i++) m = fmaxf(m, v[i]);
    red[t] = m; __syncthreads();
    for (int s = 128; s > 0; s >>= 1) { if (t < s) red[t] = fmaxf(red[t], red[t + s]); __syncthreads(); }
    m = red[0]; __syncthreads();
    float sum = 0.f;
#pragma unroll
    for (int i = 0; i < Lc / 256; i++) { v[i] = expf(v[i] - m); sum += v[i]; }
    red[t] = sum; __syncthreads();
    for (int s = 128; s > 0; s >>= 1) { if (t < s) red[t] += red[t + s]; __syncthreads(); }
    float scale = (float)Lc / red[0];
#pragma unroll
    for (int i = 0; i < Lc / 256; i++) g_alpha[bh * Lc + t + i * 256] = v[i] * scale;
}

// ================= k4: KVT[e][d] = sum_l V[l][e]*(alpha*phiK)[l][d]  (pipelined warp MMA) =================
// grid (BHc, KVS), 256 threads. Each block: 1024 l = 32 chunks of 32 rows, double-buffered smem.
#define T_KHI 0
#define T_KLO 8192
#define T_VHI 16384
#define T_VLO 24576
#define K4_BUF 32768
#define K4_KS  65536
#define K4_SMEM (65536 + 4096)

__global__ void __launch_bounds__(256) k4_mma(const float* __restrict__ phiK,
                                              const float* __restrict__ V) {
    extern __shared__ __align__(16) char smem[];
    uint32_t sb = smem_u32(smem);
    int bh = blockIdx.x, s = blockIdx.y;
    int b = bh >> 4, h = bh & 15;
    int t = threadIdx.x, lane = t & 31, w = t >> 5;

    float acc[16][4];
#pragma unroll
    for (int i = 0; i < 16; i++)
#pragma unroll
        for (int j = 0; j < 4; j++) acc[i][j] = 0.f;
    float4 ksum4 = make_float4(0.f, 0.f, 0.f, 0.f);

    const int c4 = lane;
    const int rg = w;
    const int NCH = (Lc / KVS) / 32;   // 32

    float4 kvst[4], vvst[4];
    float ast[4];

    auto STAGE = [&](int chunk) {
        int l0 = s * (Lc / KVS) + chunk * 32;
#pragma unroll
        for (int i = 0; i < 4; i++) {
            int lr = rg + 8 * i;
            int l = l0 + lr;
            size_t off = ((size_t)(b * Lc + l) * Hc + h) * Dc + c4 * 4;
            ast[i] = g_alpha[bh * Lc + l];
            kvst[i] = *(const float4*)(phiK + off);
            vvst[i] = *(const float4*)(V + off);
        }
    };
    auto CVTST = [&](int buf) {
        uint32_t base = (uint32_t)(buf * K4_BUF);
#pragma unroll
        for (int i = 0; i < 4; i++) {
            int lr = rg + 8 * i;
            float a = ast[i];
            float4 kv = kvst[i];
            kv.x *= a; kv.y *= a; kv.z *= a; kv.w *= a;
            ksum4.x += kv.x; ksum4.y += kv.y; ksum4.z += kv.z; ksum4.w += kv.w;
            uint32_t wo = lr * 256 + ((((uint32_t)(c4 >> 1)) ^ (lr & 7)) << 4) + (c4 & 1) * 8;
            uint2 hi, lo;
            split4(kv, hi, lo);
            *(uint2*)(smem + base + T_KHI + wo) = hi;
            *(uint2*)(smem + base + T_KLO + wo) = lo;
            split4(vvst[i], hi, lo);
            *(uint2*)(smem + base + T_VHI + wo) = hi;
            *(uint2*)(smem + base + T_VLO + wo) = lo;
        }
    };

    int eblk = w * 2;
    int matj = lane >> 3, rr = lane & 7;
    auto MMA = [&](int buf) {
        uint32_t base = sb + (uint32_t)(buf * K4_BUF);
#pragma unroll
        for (int ks = 0; ks < 2; ks++) {
            int lb = ks * 16;
            int lA = lb + (matj >> 1) * 8 + rr;
            uint32_t aoff = lA * 256 + ((((uint32_t)(eblk + (matj & 1))) ^ (lA & 7)) << 4);
            uint32_t ah[4], al[4];
            ldsm_x4_t(ah, base + T_VHI + aoff);
            ldsm_x4_t(al, base + T_VLO + aoff);
            int lB = lb + (matj & 1) * 8 + rr;
            uint32_t brow = lB * 256;
#pragma unroll
            for (int jp = 0; jp < 8; jp++) {
                uint32_t db = (uint32_t)(jp * 2 + (matj >> 1));
                uint32_t boff = brow + ((db ^ (lB & 7)) << 4);
                uint32_t bh4[4], bl4[4];
                ldsm_x4_t(bh4, base + T_KHI + boff);
                ldsm_x4_t(bl4, base + T_KLO + boff);
                mma16816(acc[jp * 2],     ah, bh4[0], bh4[1]);
                mma16816(acc[jp * 2],     ah, bl4[0], bl4[1]);
                mma16816(acc[jp * 2],     al, bh4[0], bh4[1]);
                mma16816(acc[jp * 2 + 1], ah, bh4[2], bh4[3]);
                mma16816(acc[jp * 2 + 1], ah, bl4[2], bl4[3]);
                mma16816(acc[jp * 2 + 1], al, bh4[2], bh4[3]);
            }
        }
    };

    STAGE(0);
    CVTST(0);
    for (int c = 0; c < NCH; c++) {
        __syncthreads();                   // buf[c&1] visible; prior readers of buf[(c+1)&1] done
        if (c + 1 < NCH) STAGE(c + 1);     // LDGs issue early, hidden by MMA
        MMA(c & 1);
        if (c + 1 < NCH) CVTST((c + 1) & 1);
    }

    // ---- fused ksum partial (fixed-order, deterministic) ----
    __syncthreads();
    *(float4*)(smem + K4_KS + (rg * 128 + c4 * 4) * 4) = ksum4;
    __syncthreads();
    if (t < 128) {
        float sum = 0.f;
        const float* ks_s = (const float*)(smem + K4_KS);
#pragma unroll
        for (int g = 0; g < 8; g++) sum += ks_s[g * 128 + t];
        g_ksumpart[(s * BHc + bh) * Dc + t] = sum;
    }

    // ---- epilogue: write fp32 partials ----
    int r0 = w * 16 + (lane >> 2);
    int cc = 2 * (lane & 3);
    float* base0 = g_kvpart + (((size_t)s * BHc + bh) * Dc + r0) * Dc + cc;
    float* base1 = base0 + 8 * Dc;
#pragma unroll
    for (int j = 0; j < 16; j++) {
        *(float2*)(base0 + j * 8) = make_float2(acc[j][0], acc[j][1]);
        *(float2*)(base1 + j * 8) = make_float2(acc[j][2], acc[j][3]);
    }
}

// ================= k4b: reduce partials + split to bf16 hi/lo =================
__global__ void k4b_reduce() {
    int idx = blockIdx.x * blockDim.x + threadIdx.x;
    if (idx >= BHc * Dc * Dc) return;
    float acc = 0.f;
#pragma unroll
    for (int s = 0; s < KVS; s++) acc += g_kvpart[(size_t)s * (BHc * Dc * Dc) + idx];
    __nv_bfloat16 h, l;
    split_bf16(acc, h, l);
    g_kv_hi[idx] = h;
    g_kv_lo[idx] = l;
}

__global__ void k_ksum_reduce() {
    int idx = blockIdx.x * blockDim.x + threadIdx.x;
    if (idx >= BHc * Dc) return;
    float acc = 0.f;
#pragma unroll
    for (int s = 0; s < KVS; s++) acc += g_ksumpart[s * (BHc * Dc) + idx];
    g_ksum[idx] = acc;
}

// ================= k5: out[l][e] = (phiQ @ KVT^T) / (phiQ . ksum + eps)  (warp MMA) =================
// grid (BHc, Lc/256), 256 threads. 2 l-tiles of 128 per block; B resident; A double-buffered
// with tile-1 fill interleaved into tile-0 MMA ks-groups.
#define K5_QHI 0
#define K5_QLO 32768
#define K5_ABUF 65536
#define K5_GHI 131072
#define K5_GLO 163840
#define K5_DEN 196608
#define K5_SMEM (196608 + 1024)

__global__ void __launch_bounds__(256) k5_mma(const float* __restrict__ phiQ,
                                              float* __restrict__ out) {
    extern __shared__ __align__(16) char smem[];
    uint32_t sb = smem_u32(smem);
    int bh = blockIdx.x, lt = blockIdx.y;
    int b = bh >> 4, h = bh & 15;
    int l0 = lt * 256;
    int t = threadIdx.x, lane = t & 31, w = t >> 5;
    float* den_s = (float*)(smem + K5_DEN);

    const int c4 = lane;
    float4 ksq = *(const float4*)(g_ksum + bh * Dc + c4 * 4);

    // ---- B fill (once) ----
#pragma unroll
    for (int i = 0; i < 8; i++) {
        int seg = t + i * 256;
        int e = seg >> 4, db = seg & 15;
        size_t goff = ((size_t)bh * Dc + e) * Dc + db * 8;
        uint32_t wo = e * 256 + ((((uint32_t)db) ^ (e & 7)) << 4);
        *(uint4*)(smem + K5_GHI + wo) = *(const uint4*)(g_kv_hi + goff);
        *(uint4*)(smem + K5_GLO + wo) = *(const uint4*)(g_kv_lo + goff);
    }

    auto FILLROW = [&](int buf, int row, float4 q) {
        float part = q.x * ksq.x + q.y * ksq.y + q.z * ksq.z + q.w * ksq.w;
        part += __shfl_xor_sync(0xFFFFFFFFu, part, 16);
        part += __shfl_xor_sync(0xFFFFFFFFu, part, 8);
        part += __shfl_xor_sync(0xFFFFFFFFu, part, 4);
        part += __shfl_xor_sync(0xFFFFFFFFu, part, 2);
        part += __shfl_xor_sync(0xFFFFFFFFu, part, 1);
        if (lane == 0) den_s[buf * 128 + row] = part;
        uint32_t base = (uint32_t)(buf * K5_ABUF);
        uint32_t wo = row * 256 + ((((uint32_t)(c4 >> 1)) ^ (row & 7)) << 4) + (c4 & 1) * 8;
        uint2 hi, lo;
        split4(q, hi, lo);
        *(uint2*)(smem + base + K5_QHI + wo) = hi;
        *(uint2*)(smem + base + K5_QLO + wo) = lo;
    };

    // ---- A fill tile0 -> buf0 ----
#pragma unroll
    for (int i = 0; i < 16; i++) {
        int row = w + 8 * i;
        float4 q = *(const float4*)(phiQ + ((size_t)(b * Lc + l0 + row) * Hc + h) * Dc + c4 * 4);
        FILLROW(0, row, q);
    }
    __syncthreads();

    int mbase = w * 16;
    int matj = lane >> 3, rr = lane & 7;
    float acc[16][4];

    auto MMAKS = [&](int buf, int ks) {
        uint32_t abase = sb + (uint32_t)(buf * K5_ABUF);
        int rowA = mbase + (matj & 1) * 8 + rr;
        uint32_t kbA = (uint32_t)(ks * 2 + (matj >> 1));
        uint32_t aoff = rowA * 256 + ((kbA ^ (rowA & 7)) << 4);
        uint32_t ah[4], al[4];
        ldsm_x4(ah, abase + K5_QHI + aoff);
        ldsm_x4(al, abase + K5_QLO + aoff);
        uint32_t kbB = (uint32_t)(ks * 2 + (matj & 1));
#pragma unroll
        for (int jp = 0; jp < 8; jp++) {
            int rowB = (jp * 2 + (matj >> 1)) * 8 + rr;
            uint32_t boff = rowB * 256 + ((kbB ^ (rowB & 7)) << 4);
            uint32_t bh4[4], bl4[4];
            ldsm_x4(bh4, sb + K5_GHI + boff);
            ldsm_x4(bl4, sb + K5_GLO + boff);
            mma16816(acc[jp * 2],     ah, bh4[0], bh4[1]);
            mma16816(acc[jp * 2],     ah, bl4[0], bl4[1]);
            mma16816(acc[jp * 2],     al, bh4[0], bh4[1]);
            mma16816(acc[jp * 2 + 1], ah, bh4[2], bh4[3]);
            mma16816(acc[jp * 2 + 1], ah, bl4[2], bl4[3]);
            mma16816(acc[jp * 2 + 1], al, bh4[2], bh4[3]);
        }
    };

    for (int tile = 0; tile < 2; tile++) {
#pragma unroll
        for (int i = 0; i < 16; i++)
#pragma unroll
            for (int j = 0; j < 4; j++) acc[i][j] = 0.f;

        if (tile == 0) {
            // MMA tile0 interleaved with staged fill of tile1 -> buf1
#pragma unroll
            for (int g = 0; g < 4; g++) {
                float4 qst[4];
#pragma unroll
                for (int i = 0; i < 4; i++) {
                    int row = w + 8 * (4 * g + i);
                    qst[i] = *(const float4*)(phiQ +
                        ((size_t)(b * Lc + l0 + 128 + row) * Hc + h) * Dc + c4 * 4);
                }
                MMAKS(0, 2 * g);
                MMAKS(0, 2 * g + 1);
#pragma unroll
                for (int i = 0; i < 4; i++) FILLROW(1, w + 8 * (4 * g + i), qst[i]);
            }
        } else {
#pragma unroll
            for (int ks = 0; ks < 8; ks++) MMAKS(1, ks);
        }

        // ---- epilogue ----
        int r0 = mbase + (lane >> 2);
        int cc = 2 * (lane & 3);
        float i0 = 1.0f / (den_s[tile * 128 + r0] + EPSc);
        float i1 = 1.0f / (den_s[tile * 128 + r0 + 8] + EPSc);
        int lb0 = l0 + tile * 128;
        float* o0 = out + ((size_t)(b * Lc + lb0 + r0) * Hc + h) * Dc + cc;
        float* o1 = out + ((size_t)(b * Lc + lb0 + r0 + 8) * Hc + h) * Dc + cc;
#pragma unroll
        for (int j = 0; j < 16; j++) {
            *(float2*)(o0 + j * 8) = make_float2(acc[j][0] * i0, acc[j][1] * i0);
            *(float2*)(o1 + j * 8) = make_float2(acc[j][2] * i1, acc[j][3] * i1);
        }
        if (tile == 0) __syncthreads();   // buf1 + den tile1 visible before tile1 MMA
    }
}

// ================= launcher =================
extern "C" void kernel_launch(void* const* d_in, const int* in_sizes, int n_in,
                              void* d_out, int out_size) {
    const float* Q    = (const float*)d_in[0];
    const float* K    = (const float*)d_in[1];
    const float* V    = (const float*)d_in[2];
    const float* phiQ = (const float*)d_in[3];
    const float* phiK = (const float*)d_in[4];
    float* out = (float*)d_out;

    cudaFuncSetAttribute(k4_mma, cudaFuncAttributeMaxDynamicSharedMemorySize, K4_SMEM);
    cudaFuncSetAttribute(k5_mma, cudaFuncAttributeMaxDynamicSharedMemorySize, K5_SMEM);

    k1_qpart<<<dim3(BHc, SPLITQ), 128>>>(Q);
    k1b_qglobal<<<(BHc * Dc + 255) / 256, 256>>>();
    k2_scores<<<dim3(BHc, Lc / 256), 256>>>(K);
    k3_softmax<<<BHc, 256>>>();
    k4_mma<<<dim3(BHc, KVS), 256, K4_SMEM>>>(phiK, V);
    k_ksum_reduce<<<(BHc * Dc + 255) / 256, 256>>>();
    k4b_reduce<<<(BHc * Dc * Dc + 255) / 256, 256>>>();
    k5_mma<<<dim3(BHc, Lc / 256), 256, K5_SMEM>>>(phiQ, out);
}

// round 6
// speedup vs baseline: 2.3951x; 1.0807x over previous
#include <cuda_runtime.h>
#include <cuda_bf16.h>
#include <math.h>
#include <stdint.h>

#define Bc 4
#define Lc 4096
#define Hc 16
#define Dc 128
#define BHc 64
#define SPLITQ 8
#define KVS 4
#define EPSc 1e-6f

// ---------------- device scratch ----------------
__device__ float g_qpart[BHc * SPLITQ * Dc];
__device__ float g_qglobal[BHc * Dc];
__device__ float g_alpha[BHc * Lc];
__device__ float g_kvpart[(size_t)KVS * BHc * Dc * Dc];
__device__ __nv_bfloat16 g_kv_hi[BHc * Dc * Dc];
__device__ __nv_bfloat16 g_kv_lo[BHc * Dc * Dc];
__device__ float g_ksumpart[KVS * BHc * Dc];
__device__ float g_ksum[BHc * Dc];

// ---------------- helpers ----------------
__device__ __forceinline__ uint32_t smem_u32(const void* p) {
    uint32_t a;
    asm("{ .reg .u64 t; cvta.to.shared.u64 t, %1; cvt.u32.u64 %0, t; }" : "=r"(a) : "l"(p));
    return a;
}
__device__ __forceinline__ void ldsm_x4(uint32_t r[4], uint32_t addr) {
    asm volatile("ldmatrix.sync.aligned.m8n8.x4.shared.b16 {%0,%1,%2,%3}, [%4];"
                 : "=r"(r[0]), "=r"(r[1]), "=r"(r[2]), "=r"(r[3]) : "r"(addr));
}
__device__ __forceinline__ void ldsm_x4_t(uint32_t r[4], uint32_t addr) {
    asm volatile("ldmatrix.sync.aligned.m8n8.x4.trans.shared.b16 {%0,%1,%2,%3}, [%4];"
                 : "=r"(r[0]), "=r"(r[1]), "=r"(r[2]), "=r"(r[3]) : "r"(addr));
}
__device__ __forceinline__ void mma16816(float c[4], const uint32_t a[4], uint32_t b0, uint32_t b1) {
    asm volatile(
        "mma.sync.aligned.m16n8k16.row.col.f32.bf16.bf16.f32 "
        "{%0,%1,%2,%3}, {%4,%5,%6,%7}, {%8,%9}, {%0,%1,%2,%3};"
        : "+f"(c[0]), "+f"(c[1]), "+f"(c[2]), "+f"(c[3])
        : "r"(a[0]), "r"(a[1]), "r"(a[2]), "r"(a[3]), "r"(b0), "r"(b1));
}
__device__ __forceinline__ void split_bf16(float x, __nv_bfloat16& h, __nv_bfloat16& l) {
    h = __float2bfloat16(x);
    l = __float2bfloat16(x - __bfloat162float(h));
}
__device__ __forceinline__ uint32_t pack_bf16(__nv_bfloat16 a, __nv_bfloat16 b) {
    __nv_bfloat162 t;
    t.x = a; t.y = b;
    return *reinterpret_cast<uint32_t*>(&t);
}
__device__ __forceinline__ void split4(float4 v, uint2& hi, uint2& lo) {
    __nv_bfloat16 h0, l0, h1, l1, h2, l2, h3, l3;
    split_bf16(v.x, h0, l0); split_bf16(v.y, h1, l1);
    split_bf16(v.z, h2, l2); split_bf16(v.w, h3, l3);
    hi.x = pack_bf16(h0, h1); hi.y = pack_bf16(h2, h3);
    lo.x = pack_bf16(l0, l1); lo.y = pack_bf16(l2, l3);
}

// ================= K1: partial sum of Q over L =================
__global__ void k1_qpart(const float* __restrict__ Q) {
    int bh = blockIdx.x, s = blockIdx.y, d = threadIdx.x;
    int b = bh >> 4, h = bh & 15;
    int l0 = s * (Lc / SPLITQ);
    const float* p = Q + ((size_t)(b * Lc + l0) * Hc + h) * Dc + d;
    float acc = 0.f;
#pragma unroll 8
    for (int i = 0; i < Lc / SPLITQ; i++) { acc += *p; p += Hc * Dc; }
    g_qpart[(bh * SPLITQ + s) * Dc + d] = acc;
}

__global__ void k1b_qglobal() {
    int idx = blockIdx.x * blockDim.x + threadIdx.x;
    if (idx >= BHc * Dc) return;
    int bh = idx / Dc, d = idx % Dc;
    float acc = 0.f;
#pragma unroll
    for (int s = 0; s < SPLITQ; s++) acc += g_qpart[(bh * SPLITQ + s) * Dc + d];
    const float scale = 1.0f / ((float)Lc * sqrtf(2048.0f));
    g_qglobal[bh * Dc + d] = acc * scale;
}

// ================= K2: scores =================
__global__ void k2_scores(const float* __restrict__ K) {
    int bh = blockIdx.x;
    int b = bh >> 4, h = bh & 15;
    int warp = threadIdx.x >> 5, lane = threadIdx.x & 31;
    float4 q = *(const float4*)&g_qglobal[bh * Dc + lane * 4];
    int l0 = blockIdx.y * 256 + warp * 32;
#pragma unroll 4
    for (int i = 0; i < 32; i++) {
        int l = l0 + i;
        const float4 kk = *(const float4*)(K + ((size_t)(b * Lc + l) * Hc + h) * Dc + lane * 4);
        float p = q.x * kk.x + q.y * kk.y + q.z * kk.z + q.w * kk.w;
        p += __shfl_xor_sync(0xFFFFFFFFu, p, 16);
        p += __shfl_xor_sync(0xFFFFFFFFu, p, 8);
        p += __shfl_xor_sync(0xFFFFFFFFu, p, 4);
        p += __shfl_xor_sync(0xFFFFFFFFu, p, 2);
        p += __shfl_xor_sync(0xFFFFFFFFu, p, 1);
        if (lane == 0) g_alpha[bh * Lc + l] = p;
    }
}

// ================= K3: softmax * L =================
__global__ void k3_softmax() {
    int bh = blockIdx.x, t = threadIdx.x;
    __shared__ float red[256];
    float v[Lc / 256];
#pragma unroll
    for (int i = 0; i < Lc / 256; i++) v[i] = g_alpha[bh * Lc + t + i * 256];
    float m = -1e30f;
#pragma unroll
    for (int i = 0; i < Lc / 256; i++) m = fmaxf(m, v[i]);
    red[t] = m; __syncthreads();
    for (int s = 128; s > 0; s >>= 1) { if (t < s) red[t] = fmaxf(red[t], red[t + s]); __syncthreads(); }
    m = red[0]; __syncthreads();
    float sum = 0.f;
#pragma unroll
    for (int i = 0; i < Lc / 256; i++) { v[i] = expf(v[i] - m); sum += v[i]; }
    red[t] = sum; __syncthreads();
    for (int s = 128; s > 0; s >>= 1) { if (t < s) red[t] += red[t + s]; __syncthreads(); }
    float scale = (float)Lc / red[0];
#pragma unroll
    for (int i = 0; i < Lc / 256; i++) g_alpha[bh * Lc + t + i * 256] = v[i] * scale;
}

// ================= k4: KVT[e][d] = sum_l V[l][e]*(alpha*phiK)[l][d] =================
// grid (BHc, KVS), 512 threads (16 warps, warp tile m16 x n64).
// Chunks of 64 l-rows, double-buffered smem (2 x 64KB), register-staged loads.
#define T_KHI 0
#define T_KLO 16384
#define T_VHI 32768
#define T_VLO 49152
#define K4_BUF 65536
#define K4_KS  131072
#define K4_SMEM (131072 + 8192)

__global__ void __launch_bounds__(512) k4_mma(const float* __restrict__ phiK,
                                              const float* __restrict__ V) {
    extern __shared__ __align__(16) char smem[];
    uint32_t sb = smem_u32(smem);
    int bh = blockIdx.x, s = blockIdx.y;
    int b = bh >> 4, h = bh & 15;
    int t = threadIdx.x, lane = t & 31, w = t >> 5;

    float acc[8][4];
#pragma unroll
    for (int i = 0; i < 8; i++)
#pragma unroll
        for (int j = 0; j < 4; j++) acc[i][j] = 0.f;
    float4 ksum4 = make_float4(0.f, 0.f, 0.f, 0.f);

    const int c4 = lane;
    const int NCH = (Lc / KVS) / 64;   // 16

    float4 kvst[4], vvst[4];
    float ast[4];

    auto STAGE = [&](int chunk) {
        int l0 = s * (Lc / KVS) + chunk * 64;
#pragma unroll
        for (int i = 0; i < 4; i++) {
            int lr = w + 16 * i;
            int l = l0 + lr;
            size_t off = ((size_t)(b * Lc + l) * Hc + h) * Dc + c4 * 4;
            ast[i] = g_alpha[bh * Lc + l];
            kvst[i] = *(const float4*)(phiK + off);
            vvst[i] = *(const float4*)(V + off);
        }
    };
    auto CVTST = [&](int buf) {
        uint32_t base = (uint32_t)(buf * K4_BUF);
#pragma unroll
        for (int i = 0; i < 4; i++) {
            int lr = w + 16 * i;
            float a = ast[i];
            float4 kv = kvst[i];
            kv.x *= a; kv.y *= a; kv.z *= a; kv.w *= a;
            ksum4.x += kv.x; ksum4.y += kv.y; ksum4.z += kv.z; ksum4.w += kv.w;
            uint32_t wo = lr * 256 + ((((uint32_t)(c4 >> 1)) ^ (lr & 7)) << 4) + (c4 & 1) * 8;
            uint2 hi, lo;
            split4(kv, hi, lo);
            *(uint2*)(smem + base + T_KHI + wo) = hi;
            *(uint2*)(smem + base + T_KLO + wo) = lo;
            split4(vvst[i], hi, lo);
            *(uint2*)(smem + base + T_VHI + wo) = hi;
            *(uint2*)(smem + base + T_VLO + wo) = lo;
        }
    };

    const int ms = w & 7, nh = w >> 3;
    const int eblk = ms * 2;
    const int matj = lane >> 3, rr = lane & 7;
    auto MMA = [&](int buf) {
        uint32_t base = sb + (uint32_t)(buf * K4_BUF);
#pragma unroll
        for (int ks = 0; ks < 4; ks++) {
            int lb = ks * 16;
            int lA = lb + (matj >> 1) * 8 + rr;
            uint32_t aoff = lA * 256 + ((((uint32_t)(eblk + (matj & 1))) ^ (lA & 7)) << 4);
            uint32_t ah[4], al[4];
            ldsm_x4_t(ah, base + T_VHI + aoff);
            ldsm_x4_t(al, base + T_VLO + aoff);
            int lB = lb + (matj & 1) * 8 + rr;
            uint32_t brow = lB * 256;
#pragma unroll
            for (int jp = 0; jp < 4; jp++) {
                uint32_t db = (uint32_t)((nh * 4 + jp) * 2 + (matj >> 1));
                uint32_t boff = brow + ((db ^ (lB & 7)) << 4);
                uint32_t bh4[4], bl4[4];
                ldsm_x4_t(bh4, base + T_KHI + boff);
                ldsm_x4_t(bl4, base + T_KLO + boff);
                mma16816(acc[jp * 2],     ah, bh4[0], bh4[1]);
                mma16816(acc[jp * 2],     ah, bl4[0], bl4[1]);
                mma16816(acc[jp * 2],     al, bh4[0], bh4[1]);
                mma16816(acc[jp * 2 + 1], ah, bh4[2], bh4[3]);
                mma16816(acc[jp * 2 + 1], ah, bl4[2], bl4[3]);
                mma16816(acc[jp * 2 + 1], al, bh4[2], bh4[3]);
            }
        }
    };

    STAGE(0);
    CVTST(0);
    for (int c = 0; c < NCH; c++) {
        __syncthreads();
        if (c + 1 < NCH) STAGE(c + 1);
        MMA(c & 1);
        if (c + 1 < NCH) CVTST((c + 1) & 1);
    }

    // ---- fused ksum partial (fixed-order, deterministic) ----
    __syncthreads();
    *(float4*)(smem + K4_KS + (w * 128 + c4 * 4) * 4) = ksum4;
    __syncthreads();
    if (t < 128) {
        float sum = 0.f;
        const float* ks_s = (const float*)(smem + K4_KS);
#pragma unroll
        for (int g = 0; g < 16; g++) sum += ks_s[g * 128 + t];
        g_ksumpart[(s * BHc + bh) * Dc + t] = sum;
    }

    // ---- epilogue: write fp32 partials ----
    int r0 = ms * 16 + (lane >> 2);
    int cc = nh * 64 + 2 * (lane & 3);
    float* base0 = g_kvpart + (((size_t)s * BHc + bh) * Dc + r0) * Dc + cc;
    float* base1 = base0 + 8 * Dc;
#pragma unroll
    for (int j = 0; j < 8; j++) {
        *(float2*)(base0 + j * 8) = make_float2(acc[j][0], acc[j][1]);
        *(float2*)(base1 + j * 8) = make_float2(acc[j][2], acc[j][3]);
    }
}

// ================= k4b: reduce partials + split to bf16 hi/lo =================
__global__ void k4b_reduce() {
    int idx = blockIdx.x * blockDim.x + threadIdx.x;
    if (idx >= BHc * Dc * Dc) return;
    float acc = 0.f;
#pragma unroll
    for (int s = 0; s < KVS; s++) acc += g_kvpart[(size_t)s * (BHc * Dc * Dc) + idx];
    __nv_bfloat16 h, l;
    split_bf16(acc, h, l);
    g_kv_hi[idx] = h;
    g_kv_lo[idx] = l;
}

__global__ void k_ksum_reduce() {
    int idx = blockIdx.x * blockDim.x + threadIdx.x;
    if (idx >= BHc * Dc) return;
    float acc = 0.f;
#pragma unroll
    for (int s = 0; s < KVS; s++) acc += g_ksumpart[s * (BHc * Dc) + idx];
    g_ksum[idx] = acc;
}

// ================= k5: out[l][e] = (phiQ @ KVT^T) / (phiQ . ksum + eps) =================
// grid (BHc, Lc/512), 512 threads (16 warps, warp tile m16 x n64).
// 4 l-tiles of 128 per block; B resident; A double-buffered, fill interleaved with MMA.
#define K5_QHI 0
#define K5_QLO 32768
#define K5_ABUF 65536
#define K5_GHI 131072
#define K5_GLO 163840
#define K5_DEN 196608
#define K5_SMEM (196608 + 1024)

__global__ void __launch_bounds__(512) k5_mma(const float* __restrict__ phiQ,
                                              float* __restrict__ out) {
    extern __shared__ __align__(16) char smem[];
    uint32_t sb = smem_u32(smem);
    int bh = blockIdx.x, lt = blockIdx.y;
    int b = bh >> 4, h = bh & 15;
    int l0 = lt * 512;
    int t = threadIdx.x, lane = t & 31, w = t >> 5;
    float* den_s = (float*)(smem + K5_DEN);

    const int c4 = lane;
    float4 ksq = *(const float4*)(g_ksum + bh * Dc + c4 * 4);

    // ---- B fill (once) ----
#pragma unroll
    for (int i = 0; i < 4; i++) {
        int seg = t + i * 512;
        int e = seg >> 4, db = seg & 15;
        size_t goff = ((size_t)bh * Dc + e) * Dc + db * 8;
        uint32_t wo = e * 256 + ((((uint32_t)db) ^ (e & 7)) << 4);
        *(uint4*)(smem + K5_GHI + wo) = *(const uint4*)(g_kv_hi + goff);
        *(uint4*)(smem + K5_GLO + wo) = *(const uint4*)(g_kv_lo + goff);
    }

    auto FILLROW = [&](int buf, int row, float4 q) {
        float part = q.x * ksq.x + q.y * ksq.y + q.z * ksq.z + q.w * ksq.w;
        part += __shfl_xor_sync(0xFFFFFFFFu, part, 16);
        part += __shfl_xor_sync(0xFFFFFFFFu, part, 8);
        part += __shfl_xor_sync(0xFFFFFFFFu, part, 4);
        part += __shfl_xor_sync(0xFFFFFFFFu, part, 2);
        part += __shfl_xor_sync(0xFFFFFFFFu, part, 1);
        if (lane == 0) den_s[buf * 128 + row] = part;
        uint32_t base = (uint32_t)(buf * K5_ABUF);
        uint32_t wo = row * 256 + ((((uint32_t)(c4 >> 1)) ^ (row & 7)) << 4) + (c4 & 1) * 8;
        uint2 hi, lo;
        split4(q, hi, lo);
        *(uint2*)(smem + base + K5_QHI + wo) = hi;
        *(uint2*)(smem + base + K5_QLO + wo) = lo;
    };

    // ---- A fill tile0 -> buf0 ----
#pragma unroll
    for (int i = 0; i < 8; i++) {
        int row = w + 16 * i;
        float4 q = *(const float4*)(phiQ + ((size_t)(b * Lc + l0 + row) * Hc + h) * Dc + c4 * 4);
        FILLROW(0, row, q);
    }
    __syncthreads();

    const int ms = w & 7, nh = w >> 3;
    const int mbase = ms * 16;
    const int matj = lane >> 3, rr = lane & 7;
    float acc[8][4];

    auto MMAKS = [&](int buf, int ks) {
        uint32_t abase = sb + (uint32_t)(buf * K5_ABUF);
        int rowA = mbase + (matj & 1) * 8 + rr;
        uint32_t kbA = (uint32_t)(ks * 2 + (matj >> 1));
        uint32_t aoff = rowA * 256 + ((kbA ^ (rowA & 7)) << 4);
        uint32_t ah[4], al[4];
        ldsm_x4(ah, abase + K5_QHI + aoff);
        ldsm_x4(al, abase + K5_QLO + aoff);
        uint32_t kbB = (uint32_t)(ks * 2 + (matj & 1));
#pragma unroll
        for (int jp = 0; jp < 4; jp++) {
            int rowB = ((nh * 4 + jp) * 2 + (matj >> 1)) * 8 + rr;
            uint32_t boff = rowB * 256 + ((kbB ^ (rowB & 7)) << 4);
            uint32_t bh4[4], bl4[4];
            ldsm_x4(bh4, sb + K5_GHI + boff);
            ldsm_x4(bl4, sb + K5_GLO + boff);
            mma16816(acc[jp * 2],     ah, bh4[0], bh4[1]);
            mma16816(acc[jp * 2],     ah, bl4[0], bl4[1]);
            mma16816(acc[jp * 2],     al, bh4[0], bh4[1]);
            mma16816(acc[jp * 2 + 1], ah, bh4[2], bh4[3]);
            mma16816(acc[jp * 2 + 1], ah, bl4[2], bl4[3]);
            mma16816(acc[jp * 2 + 1], al, bh4[2], bh4[3]);
        }
    };

    for (int tile = 0; tile < 4; tile++) {
        int buf = tile & 1, nbuf = buf ^ 1;
#pragma unroll
        for (int i = 0; i < 8; i++)
#pragma unroll
            for (int j = 0; j < 4; j++) acc[i][j] = 0.f;

        if (tile < 3) {
            // MMA on this tile interleaved with staged fill of next tile
#pragma unroll
            for (int g = 0; g < 8; g++) {
                int row = w + 16 * g;
                float4 qst = *(const float4*)(phiQ +
                    ((size_t)(b * Lc + l0 + (tile + 1) * 128 + row) * Hc + h) * Dc + c4 * 4);
                MMAKS(buf, g);
                FILLROW(nbuf, row, qst);
            }
        } else {
#pragma unroll
            for (int ks = 0; ks < 8; ks++) MMAKS(buf, ks);
        }

        // ---- epilogue ----
        int r0 = mbase + (lane >> 2);
        int cc = nh * 64 + 2 * (lane & 3);
        float i0 = 1.0f / (den_s[buf * 128 + r0] + EPSc);
        float i1 = 1.0f / (den_s[buf * 128 + r0 + 8] + EPSc);
        int lb0 = l0 + tile * 128;
        float* o0 = out + ((size_t)(b * Lc + lb0 + r0) * Hc + h) * Dc + cc;
        float* o1 = out + ((size_t)(b * Lc + lb0 + r0 + 8) * Hc + h) * Dc + cc;
#pragma unroll
        for (int j = 0; j < 8; j++) {
            *(float2*)(o0 + j * 8) = make_float2(acc[j][0] * i0, acc[j][1] * i0);
            *(float2*)(o1 + j * 8) = make_float2(acc[j][2] * i1, acc[j][3] * i1);
        }
        if (tile < 3) __syncthreads();   // next buffer fully written; current buffer free
    }
}

// ================= launcher =================
extern "C" void kernel_launch(void* const* d_in, const int* in_sizes, int n_in,
                              void* d_out, int out_size) {
    const float* Q    = (const float*)d_in[0];
    const float* K    = (const float*)d_in[1];
    const float* V    = (const float*)d_in[2];
    const float* phiQ = (const float*)d_in[3];
    const float* phiK = (const float*)d_in[4];
    float* out = (float*)d_out;

    cudaFuncSetAttribute(k4_mma, cudaFuncAttributeMaxDynamicSharedMemorySize, K4_SMEM);
    cudaFuncSetAttribute(k5_mma, cudaFuncAttributeMaxDynamicSharedMemorySize, K5_SMEM);

    k1_qpart<<<dim3(BHc, SPLITQ), 128>>>(Q);
    k1b_qglobal<<<(BHc * Dc + 255) / 256, 256>>>();
    k2_scores<<<dim3(BHc, Lc / 256), 256>>>(K);
    k3_softmax<<<BHc, 256>>>();
    k4_mma<<<dim3(BHc, KVS), 512, K4_SMEM>>>(phiK, V);
    k_ksum_reduce<<<(BHc * Dc + 255) / 256, 256>>>();
    k4b_reduce<<<(BHc * Dc * Dc + 255) / 256, 256>>>();
    k5_mma<<<dim3(BHc, Lc / 512), 512, K5_SMEM>>>(phiQ, out);
}

// round 7
// speedup vs baseline: 2.4986x; 1.0432x over previous
#include <cuda_runtime.h>
#include <cuda_bf16.h>
#include <math.h>
#include <stdint.h>

#define Bc 4
#define Lc 4096
#define Hc 16
#define Dc 128
#define BHc 64
#define SPLITQ 8
#define KVS 2
#define EPSc 1e-6f

// ---------------- device scratch ----------------
__device__ float g_qpart[BHc * SPLITQ * Dc];
__device__ float g_alpha[BHc * Lc];
__device__ float g_kvpart[(size_t)KVS * BHc * Dc * Dc];
__device__ __nv_bfloat16 g_kv_hi[BHc * Dc * Dc];
__device__ __nv_bfloat16 g_kv_lo[BHc * Dc * Dc];
__device__ float g_ksumpart[KVS * BHc * Dc];
__device__ float g_ksum[BHc * Dc];

// ---------------- helpers ----------------
__device__ __forceinline__ uint32_t smem_u32(const void* p) {
    uint32_t a;
    asm("{ .reg .u64 t; cvta.to.shared.u64 t, %1; cvt.u32.u64 %0, t; }" : "=r"(a) : "l"(p));
    return a;
}
__device__ __forceinline__ void ldsm_x4(uint32_t r[4], uint32_t addr) {
    asm volatile("ldmatrix.sync.aligned.m8n8.x4.shared.b16 {%0,%1,%2,%3}, [%4];"
                 : "=r"(r[0]), "=r"(r[1]), "=r"(r[2]), "=r"(r[3]) : "r"(addr));
}
__device__ __forceinline__ void ldsm_x4_t(uint32_t r[4], uint32_t addr) {
    asm volatile("ldmatrix.sync.aligned.m8n8.x4.trans.shared.b16 {%0,%1,%2,%3}, [%4];"
                 : "=r"(r[0]), "=r"(r[1]), "=r"(r[2]), "=r"(r[3]) : "r"(addr));
}
__device__ __forceinline__ void mma16816(float c[4], const uint32_t a[4], uint32_t b0, uint32_t b1) {
    asm volatile(
        "mma.sync.aligned.m16n8k16.row.col.f32.bf16.bf16.f32 "
        "{%0,%1,%2,%3}, {%4,%5,%6,%7}, {%8,%9}, {%0,%1,%2,%3};"
        : "+f"(c[0]), "+f"(c[1]), "+f"(c[2]), "+f"(c[3])
        : "r"(a[0]), "r"(a[1]), "r"(a[2]), "r"(a[3]), "r"(b0), "r"(b1));
}
__device__ __forceinline__ void split_bf16(float x, __nv_bfloat16& h, __nv_bfloat16& l) {
    h = __float2bfloat16(x);
    l = __float2bfloat16(x - __bfloat162float(h));
}
__device__ __forceinline__ uint32_t pack_bf16(__nv_bfloat16 a, __nv_bfloat16 b) {
    __nv_bfloat162 t;
    t.x = a; t.y = b;
    return *reinterpret_cast<uint32_t*>(&t);
}
__device__ __forceinline__ void split4(float4 v, uint2& hi, uint2& lo) {
    __nv_bfloat16 h0, l0, h1, l1, h2, l2, h3, l3;
    split_bf16(v.x, h0, l0); split_bf16(v.y, h1, l1);
    split_bf16(v.z, h2, l2); split_bf16(v.w, h3, l3);
    hi.x = pack_bf16(h0, h1); hi.y = pack_bf16(h2, h3);
    lo.x = pack_bf16(l0, l1); lo.y = pack_bf16(l2, l3);
}

// ================= K1: partial sum of Q over L =================
__global__ void k1_qpart(const float* __restrict__ Q) {
    int bh = blockIdx.x, s = blockIdx.y, d = threadIdx.x;
    int b = bh >> 4, h = bh & 15;
    int l0 = s * (Lc / SPLITQ);
    const float* p = Q + ((size_t)(b * Lc + l0) * Hc + h) * Dc + d;
    float acc = 0.f;
#pragma unroll 8
    for (int i = 0; i < Lc / SPLITQ; i++) { acc += *p; p += Hc * Dc; }
    g_qpart[(bh * SPLITQ + s) * Dc + d] = acc;
}

// ================= K2: scores (q_global folded in) =================
__global__ void k2_scores(const float* __restrict__ K) {
    __shared__ float qg[Dc];
    int bh = blockIdx.x;
    int b = bh >> 4, h = bh & 15;
    int t = threadIdx.x, warp = t >> 5, lane = t & 31;
    if (t < Dc) {
        float acc = 0.f;
#pragma unroll
        for (int s = 0; s < SPLITQ; s++) acc += g_qpart[(bh * SPLITQ + s) * Dc + t];
        qg[t] = acc * (1.0f / ((float)Lc * sqrtf(2048.0f)));
    }
    __syncthreads();
    float4 q = *(const float4*)&qg[lane * 4];
    int l0 = blockIdx.y * 256 + warp * 32;
#pragma unroll 4
    for (int i = 0; i < 32; i++) {
        int l = l0 + i;
        const float4 kk = *(const float4*)(K + ((size_t)(b * Lc + l) * Hc + h) * Dc + lane * 4);
        float p = q.x * kk.x + q.y * kk.y + q.z * kk.z + q.w * kk.w;
        p += __shfl_xor_sync(0xFFFFFFFFu, p, 16);
        p += __shfl_xor_sync(0xFFFFFFFFu, p, 8);
        p += __shfl_xor_sync(0xFFFFFFFFu, p, 4);
        p += __shfl_xor_sync(0xFFFFFFFFu, p, 2);
        p += __shfl_xor_sync(0xFFFFFFFFu, p, 1);
        if (lane == 0) g_alpha[bh * Lc + l] = p;
    }
}

// ================= K3: softmax * L =================
__global__ void k3_softmax() {
    int bh = blockIdx.x, t = threadIdx.x;
    __shared__ float red[256];
    float v[Lc / 256];
#pragma unroll
    for (int i = 0; i < Lc / 256; i++) v[i] = g_alpha[bh * Lc + t + i * 256];
    float m = -1e30f;
#pragma unroll
    for (int i = 0; i < Lc / 256; i++) m = fmaxf(m, v[i]);
    red[t] = m; __syncthreads();
    for (int s = 128; s > 0; s >>= 1) { if (t < s) red[t] = fmaxf(red[t], red[t + s]); __syncthreads(); }
    m = red[0]; __syncthreads();
    float sum = 0.f;
#pragma unroll
    for (int i = 0; i < Lc / 256; i++) { v[i] = expf(v[i] - m); sum += v[i]; }
    red[t] = sum; __syncthreads();
    for (int s = 128; s > 0; s >>= 1) { if (t < s) red[t] += red[t + s]; __syncthreads(); }
    float scale = (float)Lc / red[0];
#pragma unroll
    for (int i = 0; i < Lc / 256; i++) g_alpha[bh * Lc + t + i * 256] = v[i] * scale;
}

// ================= k4: KVT[e][d] = sum_l V[l][e]*(alpha*phiK)[l][d] =================
// grid (BHc, KVS) = 128 blocks (single wave), 512 threads (16 warps, warp tile m16 x n64).
// Chunks of 64 l-rows, double-buffered smem (2 x 64KB), register-staged loads.
#define T_KHI 0
#define T_KLO 16384
#define T_VHI 32768
#define T_VLO 49152
#define K4_BUF 65536
#define K4_KS  131072
#define K4_SMEM (131072 + 8192)

__global__ void __launch_bounds__(512) k4_mma(const float* __restrict__ phiK,
                                              const float* __restrict__ V) {
    extern __shared__ __align__(16) char smem[];
    uint32_t sb = smem_u32(smem);
    int bh = blockIdx.x, s = blockIdx.y;
    int b = bh >> 4, h = bh & 15;
    int t = threadIdx.x, lane = t & 31, w = t >> 5;

    float acc[8][4];
#pragma unroll
    for (int i = 0; i < 8; i++)
#pragma unroll
        for (int j = 0; j < 4; j++) acc[i][j] = 0.f;
    float4 ksum4 = make_float4(0.f, 0.f, 0.f, 0.f);

    const int c4 = lane;
    const int NCH = (Lc / KVS) / 64;   // 32

    float4 kvst[4], vvst[4];
    float ast[4];

    auto STAGE = [&](int chunk) {
        int l0 = s * (Lc / KVS) + chunk * 64;
#pragma unroll
        for (int i = 0; i < 4; i++) {
            int lr = w + 16 * i;
            int l = l0 + lr;
            size_t off = ((size_t)(b * Lc + l) * Hc + h) * Dc + c4 * 4;
            ast[i] = g_alpha[bh * Lc + l];
            kvst[i] = *(const float4*)(phiK + off);
            vvst[i] = *(const float4*)(V + off);
        }
    };
    auto CVTST = [&](int buf) {
        uint32_t base = (uint32_t)(buf * K4_BUF);
#pragma unroll
        for (int i = 0; i < 4; i++) {
            int lr = w + 16 * i;
            float a = ast[i];
            float4 kv = kvst[i];
            kv.x *= a; kv.y *= a; kv.z *= a; kv.w *= a;
            ksum4.x += kv.x; ksum4.y += kv.y; ksum4.z += kv.z; ksum4.w += kv.w;
            uint32_t wo = lr * 256 + ((((uint32_t)(c4 >> 1)) ^ (lr & 7)) << 4) + (c4 & 1) * 8;
            uint2 hi, lo;
            split4(kv, hi, lo);
            *(uint2*)(smem + base + T_KHI + wo) = hi;
            *(uint2*)(smem + base + T_KLO + wo) = lo;
            split4(vvst[i], hi, lo);
            *(uint2*)(smem + base + T_VHI + wo) = hi;
            *(uint2*)(smem + base + T_VLO + wo) = lo;
        }
    };

    const int ms = w & 7, nh = w >> 3;
    const int eblk = ms * 2;
    const int matj = lane >> 3, rr = lane & 7;
    auto MMA = [&](int buf) {
        uint32_t base = sb + (uint32_t)(buf * K4_BUF);
#pragma unroll
        for (int ks = 0; ks < 4; ks++) {
            int lb = ks * 16;
            int lA = lb + (matj >> 1) * 8 + rr;
            uint32_t aoff = lA * 256 + ((((uint32_t)(eblk + (matj & 1))) ^ (lA & 7)) << 4);
            uint32_t ah[4], al[4];
            ldsm_x4_t(ah, base + T_VHI + aoff);
            ldsm_x4_t(al, base + T_VLO + aoff);
            int lB = lb + (matj & 1) * 8 + rr;
            uint32_t brow = lB * 256;
#pragma unroll
            for (int jp = 0; jp < 4; jp++) {
                uint32_t db = (uint32_t)((nh * 4 + jp) * 2 + (matj >> 1));
                uint32_t boff = brow + ((db ^ (lB & 7)) << 4);
                uint32_t bh4[4], bl4[4];
                ldsm_x4_t(bh4, base + T_KHI + boff);
                ldsm_x4_t(bl4, base + T_KLO + boff);
                mma16816(acc[jp * 2],     ah, bh4[0], bh4[1]);
                mma16816(acc[jp * 2],     ah, bl4[0], bl4[1]);
                mma16816(acc[jp * 2],     al, bh4[0], bh4[1]);
                mma16816(acc[jp * 2 + 1], ah, bh4[2], bh4[3]);
                mma16816(acc[jp * 2 + 1], ah, bl4[2], bl4[3]);
                mma16816(acc[jp * 2 + 1], al, bh4[2], bh4[3]);
            }
        }
    };

    STAGE(0);
    CVTST(0);
    for (int c = 0; c < NCH; c++) {
        __syncthreads();
        if (c + 1 < NCH) STAGE(c + 1);
        MMA(c & 1);
        if (c + 1 < NCH) CVTST((c + 1) & 1);
    }

    // ---- fused ksum partial (fixed-order, deterministic) ----
    __syncthreads();
    *(float4*)(smem + K4_KS + (w * 128 + c4 * 4) * 4) = ksum4;
    __syncthreads();
    if (t < 128) {
        float sum = 0.f;
        const float* ks_s = (const float*)(smem + K4_KS);
#pragma unroll
        for (int g = 0; g < 16; g++) sum += ks_s[g * 128 + t];
        g_ksumpart[(s * BHc + bh) * Dc + t] = sum;
    }

    // ---- epilogue: write fp32 partials ----
    int r0 = ms * 16 + (lane >> 2);
    int cc = nh * 64 + 2 * (lane & 3);
    float* base0 = g_kvpart + (((size_t)s * BHc + bh) * Dc + r0) * Dc + cc;
    float* base1 = base0 + 8 * Dc;
#pragma unroll
    for (int j = 0; j < 8; j++) {
        *(float2*)(base0 + j * 8) = make_float2(acc[j][0], acc[j][1]);
        *(float2*)(base1 + j * 8) = make_float2(acc[j][2], acc[j][3]);
    }
}

// ================= k4b: reduce partials + split to bf16 hi/lo (+ ksum reduce folded) =================
__global__ void k4b_reduce() {
    int idx = blockIdx.x * blockDim.x + threadIdx.x;
    if (idx >= BHc * Dc * Dc) return;
    float acc = 0.f;
#pragma unroll
    for (int s = 0; s < KVS; s++) acc += g_kvpart[(size_t)s * (BHc * Dc * Dc) + idx];
    __nv_bfloat16 h, l;
    split_bf16(acc, h, l);
    g_kv_hi[idx] = h;
    g_kv_lo[idx] = l;
    if (idx < BHc * Dc) {
        float ks = 0.f;
#pragma unroll
        for (int s = 0; s < KVS; s++) ks += g_ksumpart[s * (BHc * Dc) + idx];
        g_ksum[idx] = ks;
    }
}

// ================= k5: out[l][e] = (phiQ @ KVT^T) / (phiQ . ksum + eps) =================
// grid (BHc, 2) = 128 blocks (single wave), 512 threads (16 warps, warp tile m16 x n64).
// 16 l-tiles of 128 per block; B resident (filled once); A double-buffered, fill
// interleaved with MMA.
#define K5_TILES 16
#define K5_QHI 0
#define K5_QLO 32768
#define K5_ABUF 65536
#define K5_GHI 131072
#define K5_GLO 163840
#define K5_DEN 196608
#define K5_SMEM (196608 + 1024)

__global__ void __launch_bounds__(512) k5_mma(const float* __restrict__ phiQ,
                                              float* __restrict__ out) {
    extern __shared__ __align__(16) char smem[];
    uint32_t sb = smem_u32(smem);
    int bh = blockIdx.x, lt = blockIdx.y;
    int b = bh >> 4, h = bh & 15;
    int l0 = lt * (128 * K5_TILES);
    int t = threadIdx.x, lane = t & 31, w = t >> 5;
    float* den_s = (float*)(smem + K5_DEN);

    const int c4 = lane;
    float4 ksq = *(const float4*)(g_ksum + bh * Dc + c4 * 4);

    // ---- B fill (once) ----
#pragma unroll
    for (int i = 0; i < 4; i++) {
        int seg = t + i * 512;
        int e = seg >> 4, db = seg & 15;
        size_t goff = ((size_t)bh * Dc + e) * Dc + db * 8;
        uint32_t wo = e * 256 + ((((uint32_t)db) ^ (e & 7)) << 4);
        *(uint4*)(smem + K5_GHI + wo) = *(const uint4*)(g_kv_hi + goff);
        *(uint4*)(smem + K5_GLO + wo) = *(const uint4*)(g_kv_lo + goff);
    }

    auto FILLROW = [&](int buf, int row, float4 q) {
        float part = q.x * ksq.x + q.y * ksq.y + q.z * ksq.z + q.w * ksq.w;
        part += __shfl_xor_sync(0xFFFFFFFFu, part, 16);
        part += __shfl_xor_sync(0xFFFFFFFFu, part, 8);
        part += __shfl_xor_sync(0xFFFFFFFFu, part, 4);
        part += __shfl_xor_sync(0xFFFFFFFFu, part, 2);
        part += __shfl_xor_sync(0xFFFFFFFFu, part, 1);
        if (lane == 0) den_s[buf * 128 + row] = part;
        uint32_t base = (uint32_t)(buf * K5_ABUF);
        uint32_t wo = row * 256 + ((((uint32_t)(c4 >> 1)) ^ (row & 7)) << 4) + (c4 & 1) * 8;
        uint2 hi, lo;
        split4(q, hi, lo);
        *(uint2*)(smem + base + K5_QHI + wo) = hi;
        *(uint2*)(smem + base + K5_QLO + wo) = lo;
    };

    // ---- A fill tile0 -> buf0 ----
#pragma unroll
    for (int i = 0; i < 8; i++) {
        int row = w + 16 * i;
        float4 q = *(const float4*)(phiQ + ((size_t)(b * Lc + l0 + row) * Hc + h) * Dc + c4 * 4);
        FILLROW(0, row, q);
    }
    __syncthreads();

    const int ms = w & 7, nh = w >> 3;
    const int mbase = ms * 16;
    const int matj = lane >> 3, rr = lane & 7;
    float acc[8][4];

    auto MMAKS = [&](int buf, int ks) {
        uint32_t abase = sb + (uint32_t)(buf * K5_ABUF);
        int rowA = mbase + (matj & 1) * 8 + rr;
        uint32_t kbA = (uint32_t)(ks * 2 + (matj >> 1));
        uint32_t aoff = rowA * 256 + ((kbA ^ (rowA & 7)) << 4);
        uint32_t ah[4], al[4];
        ldsm_x4(ah, abase + K5_QHI + aoff);
        ldsm_x4(al, abase + K5_QLO + aoff);
        uint32_t kbB = (uint32_t)(ks * 2 + (matj & 1));
#pragma unroll
        for (int jp = 0; jp < 4; jp++) {
            int rowB = ((nh * 4 + jp) * 2 + (matj >> 1)) * 8 + rr;
            uint32_t boff = rowB * 256 + ((kbB ^ (rowB & 7)) << 4);
            uint32_t bh4[4], bl4[4];
            ldsm_x4(bh4, sb + K5_GHI + boff);
            ldsm_x4(bl4, sb + K5_GLO + boff);
            mma16816(acc[jp * 2],     ah, bh4[0], bh4[1]);
            mma16816(acc[jp * 2],     ah, bl4[0], bl4[1]);
            mma16816(acc[jp * 2],     al, bh4[0], bh4[1]);
            mma16816(acc[jp * 2 + 1], ah, bh4[2], bh4[3]);
            mma16816(acc[jp * 2 + 1], ah, bl4[2], bl4[3]);
            mma16816(acc[jp * 2 + 1], al, bh4[2], bh4[3]);
        }
    };

    for (int tile = 0; tile < K5_TILES; tile++) {
        int buf = tile & 1, nbuf = buf ^ 1;
#pragma unroll
        for (int i = 0; i < 8; i++)
#pragma unroll
            for (int j = 0; j < 4; j++) acc[i][j] = 0.f;

        if (tile < K5_TILES - 1) {
            // MMA on this tile interleaved with staged fill of next tile
#pragma unroll
            for (int g = 0; g < 8; g++) {
                int row = w + 16 * g;
                float4 qst = *(const float4*)(phiQ +
                    ((size_t)(b * Lc + l0 + (tile + 1) * 128 + row) * Hc + h) * Dc + c4 * 4);
                MMAKS(buf, g);
                FILLROW(nbuf, row, qst);
            }
        } else {
#pragma unroll
            for (int ks = 0; ks < 8; ks++) MMAKS(buf, ks);
        }

        // ---- epilogue ----
        int r0 = mbase + (lane >> 2);
        int cc = nh * 64 + 2 * (lane & 3);
        float i0 = 1.0f / (den_s[buf * 128 + r0] + EPSc);
        float i1 = 1.0f / (den_s[buf * 128 + r0 + 8] + EPSc);
        int lb0 = l0 + tile * 128;
        float* o0 = out + ((size_t)(b * Lc + lb0 + r0) * Hc + h) * Dc + cc;
        float* o1 = out + ((size_t)(b * Lc + lb0 + r0 + 8) * Hc + h) * Dc + cc;
#pragma unroll
        for (int j = 0; j < 8; j++) {
            *(float2*)(o0 + j * 8) = make_float2(acc[j][0] * i0, acc[j][1] * i0);
            *(float2*)(o1 + j * 8) = make_float2(acc[j][2] * i1, acc[j][3] * i1);
        }
        if (tile < K5_TILES - 1) __syncthreads();   // next buffer written; current buffer free
    }
}

// ================= launcher =================
extern "C" void kernel_launch(void* const* d_in, const int* in_sizes, int n_in,
                              void* d_out, int out_size) {
    const float* Q    = (const float*)d_in[0];
    const float* K    = (const float*)d_in[1];
    const float* V    = (const float*)d_in[2];
    const float* phiQ = (const float*)d_in[3];
    const float* phiK = (const float*)d_in[4];
    float* out = (float*)d_out;

    cudaFuncSetAttribute(k4_mma, cudaFuncAttributeMaxDynamicSharedMemorySize, K4_SMEM);
    cudaFuncSetAttribute(k5_mma, cudaFuncAttributeMaxDynamicSharedMemorySize, K5_SMEM);

    k1_qpart<<<dim3(BHc, SPLITQ), 128>>>(Q);
    k2_scores<<<dim3(BHc, Lc / 256), 256>>>(K);
    k3_softmax<<<BHc, 256>>>();
    k4_mma<<<dim3(BHc, KVS), 512, K4_SMEM>>>(phiK, V);
    k4b_reduce<<<(BHc * Dc * Dc + 255) / 256, 256>>>();
    k5_mma<<<dim3(BHc, 2), 512, K5_SMEM>>>(phiQ, out);
}

// round 8
// speedup vs baseline: 2.5940x; 1.0382x over previous
#include <cuda_runtime.h>
#include <cuda_bf16.h>
#include <math.h>
#include <stdint.h>

#define Bc 4
#define Lc 4096
#define Hc 16
#define Dc 128
#define BHc 64
#define SPLITQ 8
#define KVS 2
#define EPSc 1e-6f

// ---------------- device scratch ----------------
__device__ float g_qpart[BHc * SPLITQ * Dc];
__device__ float g_alpha[BHc * Lc];
__device__ float g_kvpart[(size_t)KVS * BHc * Dc * Dc];
__device__ __nv_bfloat16 g_kv_hi[BHc * Dc * Dc];
__device__ __nv_bfloat16 g_kv_lo[BHc * Dc * Dc];
__device__ float g_ksumpart[KVS * BHc * Dc];
__device__ float g_ksum[BHc * Dc];

// ---------------- helpers ----------------
__device__ __forceinline__ uint32_t smem_u32(const void* p) {
    uint32_t a;
    asm("{ .reg .u64 t; cvta.to.shared.u64 t, %1; cvt.u32.u64 %0, t; }" : "=r"(a) : "l"(p));
    return a;
}
__device__ __forceinline__ void ldsm_x4(uint32_t r[4], uint32_t addr) {
    asm volatile("ldmatrix.sync.aligned.m8n8.x4.shared.b16 {%0,%1,%2,%3}, [%4];"
                 : "=r"(r[0]), "=r"(r[1]), "=r"(r[2]), "=r"(r[3]) : "r"(addr));
}
__device__ __forceinline__ void ldsm_x4_t(uint32_t r[4], uint32_t addr) {
    asm volatile("ldmatrix.sync.aligned.m8n8.x4.trans.shared.b16 {%0,%1,%2,%3}, [%4];"
                 : "=r"(r[0]), "=r"(r[1]), "=r"(r[2]), "=r"(r[3]) : "r"(addr));
}
__device__ __forceinline__ void mma16816(float c[4], const uint32_t a[4], uint32_t b0, uint32_t b1) {
    asm volatile(
        "mma.sync.aligned.m16n8k16.row.col.f32.bf16.bf16.f32 "
        "{%0,%1,%2,%3}, {%4,%5,%6,%7}, {%8,%9}, {%0,%1,%2,%3};"
        : "+f"(c[0]), "+f"(c[1]), "+f"(c[2]), "+f"(c[3])
        : "r"(a[0]), "r"(a[1]), "r"(a[2]), "r"(a[3]), "r"(b0), "r"(b1));
}
__device__ __forceinline__ void split_bf16(float x, __nv_bfloat16& h, __nv_bfloat16& l) {
    h = __float2bfloat16(x);
    l = __float2bfloat16(x - __bfloat162float(h));
}
__device__ __forceinline__ uint32_t pack_bf16(__nv_bfloat16 a, __nv_bfloat16 b) {
    __nv_bfloat162 t;
    t.x = a; t.y = b;
    return *reinterpret_cast<uint32_t*>(&t);
}
__device__ __forceinline__ void split4(float4 v, uint2& hi, uint2& lo) {
    __nv_bfloat16 h0, l0, h1, l1, h2, l2, h3, l3;
    split_bf16(v.x, h0, l0); split_bf16(v.y, h1, l1);
    split_bf16(v.z, h2, l2); split_bf16(v.w, h3, l3);
    hi.x = pack_bf16(h0, h1); hi.y = pack_bf16(h2, h3);
    lo.x = pack_bf16(l0, l1); lo.y = pack_bf16(l2, l3);
}

// ================= K1: partial sum of Q over L =================
__global__ void k1_qpart(const float* __restrict__ Q) {
    int bh = blockIdx.x, s = blockIdx.y, d = threadIdx.x;
    int b = bh >> 4, h = bh & 15;
    int l0 = s * (Lc / SPLITQ);
    const float* p = Q + ((size_t)(b * Lc + l0) * Hc + h) * Dc + d;
    float acc = 0.f;
#pragma unroll 8
    for (int i = 0; i < Lc / SPLITQ; i++) { acc += *p; p += Hc * Dc; }
    g_qpart[(bh * SPLITQ + s) * Dc + d] = acc;
}

// ================= K2: scores (q_global folded in) =================
__global__ void k2_scores(const float* __restrict__ K) {
    __shared__ float qg[Dc];
    int bh = blockIdx.x;
    int b = bh >> 4, h = bh & 15;
    int t = threadIdx.x, warp = t >> 5, lane = t & 31;
    if (t < Dc) {
        float acc = 0.f;
#pragma unroll
        for (int s = 0; s < SPLITQ; s++) acc += g_qpart[(bh * SPLITQ + s) * Dc + t];
        qg[t] = acc * (1.0f / ((float)Lc * sqrtf(2048.0f)));
    }
    __syncthreads();
    float4 q = *(const float4*)&qg[lane * 4];
    int l0 = blockIdx.y * 256 + warp * 32;
#pragma unroll 4
    for (int i = 0; i < 32; i++) {
        int l = l0 + i;
        const float4 kk = *(const float4*)(K + ((size_t)(b * Lc + l) * Hc + h) * Dc + lane * 4);
        float p = q.x * kk.x + q.y * kk.y + q.z * kk.z + q.w * kk.w;
        p += __shfl_xor_sync(0xFFFFFFFFu, p, 16);
        p += __shfl_xor_sync(0xFFFFFFFFu, p, 8);
        p += __shfl_xor_sync(0xFFFFFFFFu, p, 4);
        p += __shfl_xor_sync(0xFFFFFFFFu, p, 2);
        p += __shfl_xor_sync(0xFFFFFFFFu, p, 1);
        if (lane == 0) g_alpha[bh * Lc + l] = p;
    }
}

// ================= K3: softmax * L =================
__global__ void k3_softmax() {
    int bh = blockIdx.x, t = threadIdx.x;
    __shared__ float red[256];
    float v[Lc / 256];
#pragma unroll
    for (int i = 0; i < Lc / 256; i++) v[i] = g_alpha[bh * Lc + t + i * 256];
    float m = -1e30f;
#pragma unroll
    for (int i = 0; i < Lc / 256; i++) m = fmaxf(m, v[i]);
    red[t] = m; __syncthreads();
    for (int s = 128; s > 0; s >>= 1) { if (t < s) red[t] = fmaxf(red[t], red[t + s]); __syncthreads(); }
    m = red[0]; __syncthreads();
    float sum = 0.f;
#pragma unroll
    for (int i = 0; i < Lc / 256; i++) { v[i] = expf(v[i] - m); sum += v[i]; }
    red[t] = sum; __syncthreads();
    for (int s = 128; s > 0; s >>= 1) { if (t < s) red[t] += red[t + s]; __syncthreads(); }
    float scale = (float)Lc / red[0];
#pragma unroll
    for (int i = 0; i < Lc / 256; i++) g_alpha[bh * Lc + t + i * 256] = v[i] * scale;
}

// ================= k4: KVT[e][d] = sum_l V[l][e]*(alpha*phiK)[l][d] =================
// grid (BHc, KVS) = 128 blocks, 512 threads. Warp grid 4x4, warp tile m32 x n32.
// Chunks of 64 l-rows, double-buffered smem, register-staged loads.
#define T_KHI 0
#define T_KLO 16384
#define T_VHI 32768
#define T_VLO 49152
#define K4_BUF 65536
#define K4_KS  131072
#define K4_SMEM (131072 + 8192)

__global__ void __launch_bounds__(512) k4_mma(const float* __restrict__ phiK,
                                              const float* __restrict__ V) {
    extern __shared__ __align__(16) char smem[];
    uint32_t sb = smem_u32(smem);
    int bh = blockIdx.x, s = blockIdx.y;
    int b = bh >> 4, h = bh & 15;
    int t = threadIdx.x, lane = t & 31, w = t >> 5;

    float acc[8][4];   // [((mi*2+ni)*2+half)][4]
#pragma unroll
    for (int i = 0; i < 8; i++)
#pragma unroll
        for (int j = 0; j < 4; j++) acc[i][j] = 0.f;
    float4 ksum4 = make_float4(0.f, 0.f, 0.f, 0.f);

    const int c4 = lane;
    const int NCH = (Lc / KVS) / 64;   // 32

    float4 kvst[4], vvst[4];
    float ast[4];

    auto STAGE = [&](int chunk) {
        int l0 = s * (Lc / KVS) + chunk * 64;
#pragma unroll
        for (int i = 0; i < 4; i++) {
            int lr = w + 16 * i;
            int l = l0 + lr;
            size_t off = ((size_t)(b * Lc + l) * Hc + h) * Dc + c4 * 4;
            ast[i] = g_alpha[bh * Lc + l];
            kvst[i] = *(const float4*)(phiK + off);
            vvst[i] = *(const float4*)(V + off);
        }
    };
    auto CVTST = [&](int buf) {
        uint32_t base = (uint32_t)(buf * K4_BUF);
#pragma unroll
        for (int i = 0; i < 4; i++) {
            int lr = w + 16 * i;
            float a = ast[i];
            float4 kv = kvst[i];
            kv.x *= a; kv.y *= a; kv.z *= a; kv.w *= a;
            ksum4.x += kv.x; ksum4.y += kv.y; ksum4.z += kv.z; ksum4.w += kv.w;
            uint32_t wo = lr * 256 + ((((uint32_t)(c4 >> 1)) ^ (lr & 7)) << 4) + (c4 & 1) * 8;
            uint2 hi, lo;
            split4(kv, hi, lo);
            *(uint2*)(smem + base + T_KHI + wo) = hi;
            *(uint2*)(smem + base + T_KLO + wo) = lo;
            split4(vvst[i], hi, lo);
            *(uint2*)(smem + base + T_VHI + wo) = hi;
            *(uint2*)(smem + base + T_VLO + wo) = lo;
        }
    };

    const int ms = w & 3, nh = w >> 2;   // 4x4 warp grid
    const int matj = lane >> 3, rr = lane & 7;
    auto MMA = [&](int buf) {
        uint32_t base = sb + (uint32_t)(buf * K4_BUF);
#pragma unroll
        for (int ks = 0; ks < 4; ks++) {
            int lb = ks * 16;
            // A (V^T) fragments: 2 m16 tiles, hi+lo
            uint32_t ah[2][4], al[2][4];
            int lA = lb + (matj >> 1) * 8 + rr;
#pragma unroll
            for (int mi = 0; mi < 2; mi++) {
                int mt = ms * 2 + mi;
                uint32_t aoff = lA * 256 + ((((uint32_t)(mt * 2 + (matj & 1))) ^ (lA & 7)) << 4);
                ldsm_x4_t(ah[mi], base + T_VHI + aoff);
                ldsm_x4_t(al[mi], base + T_VLO + aoff);
            }
            int lB = lb + (matj & 1) * 8 + rr;
            uint32_t brow = lB * 256;
#pragma unroll
            for (int ni = 0; ni < 2; ni++) {
                int nt = nh * 2 + ni;
                uint32_t boff = brow + ((((uint32_t)(nt * 2 + (matj >> 1))) ^ (lB & 7)) << 4);
                uint32_t bh4[4], bl4[4];
                ldsm_x4_t(bh4, base + T_KHI + boff);
                ldsm_x4_t(bl4, base + T_KLO + boff);
#pragma unroll
                for (int mi = 0; mi < 2; mi++) {
                    int a0 = (mi * 2 + ni) * 2;
                    mma16816(acc[a0],     ah[mi], bh4[0], bh4[1]);
                    mma16816(acc[a0],     ah[mi], bl4[0], bl4[1]);
                    mma16816(acc[a0],     al[mi], bh4[0], bh4[1]);
                    mma16816(acc[a0 + 1], ah[mi], bh4[2], bh4[3]);
                    mma16816(acc[a0 + 1], ah[mi], bl4[2], bl4[3]);
                    mma16816(acc[a0 + 1], al[mi], bh4[2], bh4[3]);
                }
            }
        }
    };

    STAGE(0);
    CVTST(0);
    for (int c = 0; c < NCH; c++) {
        __syncthreads();
        if (c + 1 < NCH) STAGE(c + 1);
        MMA(c & 1);
        if (c + 1 < NCH) CVTST((c + 1) & 1);
    }

    // ---- fused ksum partial (fixed-order, deterministic) ----
    __syncthreads();
    *(float4*)(smem + K4_KS + (w * 128 + c4 * 4) * 4) = ksum4;
    __syncthreads();
    if (t < 128) {
        float sum = 0.f;
        const float* ks_s = (const float*)(smem + K4_KS);
#pragma unroll
        for (int g = 0; g < 16; g++) sum += ks_s[g * 128 + t];
        g_ksumpart[(s * BHc + bh) * Dc + t] = sum;
    }

    // ---- epilogue: write fp32 partials ----
    int r_in = lane >> 2;
    int cc_in = 2 * (lane & 3);
#pragma unroll
    for (int mi = 0; mi < 2; mi++) {
#pragma unroll
        for (int ni = 0; ni < 2; ni++) {
#pragma unroll
            for (int half = 0; half < 2; half++) {
                const float* a = acc[(mi * 2 + ni) * 2 + half];
                int row = ms * 32 + mi * 16 + r_in;
                int col = nh * 32 + ni * 16 + half * 8 + cc_in;
                float* dst = g_kvpart + (((size_t)s * BHc + bh) * Dc + row) * Dc + col;
                *(float2*)(dst)          = make_float2(a[0], a[1]);
                *(float2*)(dst + 8 * Dc) = make_float2(a[2], a[3]);
            }
        }
    }
}

// ================= k4b: reduce partials + split to bf16 hi/lo (+ ksum reduce folded) =================
__global__ void k4b_reduce() {
    int idx = blockIdx.x * blockDim.x + threadIdx.x;
    if (idx >= BHc * Dc * Dc) return;
    float acc = 0.f;
#pragma unroll
    for (int s = 0; s < KVS; s++) acc += g_kvpart[(size_t)s * (BHc * Dc * Dc) + idx];
    __nv_bfloat16 h, l;
    split_bf16(acc, h, l);
    g_kv_hi[idx] = h;
    g_kv_lo[idx] = l;
    if (idx < BHc * Dc) {
        float ks = 0.f;
#pragma unroll
        for (int s = 0; s < KVS; s++) ks += g_ksumpart[s * (BHc * Dc) + idx];
        g_ksum[idx] = ks;
    }
}

// ================= k5: out[l][e] = (phiQ @ KVT^T) / (phiQ . ksum + eps) =================
// grid (BHc, 2) = 128 blocks, 512 threads. Warp grid 4x4, warp tile m32 x n32.
// 16 l-tiles of 128 per block; B resident; A double-buffered, fill interleaved with MMA.
#define K5_TILES 16
#define K5_QHI 0
#define K5_QLO 32768
#define K5_ABUF 65536
#define K5_GHI 131072
#define K5_GLO 163840
#define K5_DEN 196608
#define K5_SMEM (196608 + 1024)

__global__ void __launch_bounds__(512) k5_mma(const float* __restrict__ phiQ,
                                              float* __restrict__ out) {
    extern __shared__ __align__(16) char smem[];
    uint32_t sb = smem_u32(smem);
    int bh = blockIdx.x, lt = blockIdx.y;
    int b = bh >> 4, h = bh & 15;
    int l0 = lt * (128 * K5_TILES);
    int t = threadIdx.x, lane = t & 31, w = t >> 5;
    float* den_s = (float*)(smem + K5_DEN);

    const int c4 = lane;
    float4 ksq = *(const float4*)(g_ksum + bh * Dc + c4 * 4);

    // ---- B fill (once) ----
#pragma unroll
    for (int i = 0; i < 4; i++) {
        int seg = t + i * 512;
        int e = seg >> 4, db = seg & 15;
        size_t goff = ((size_t)bh * Dc + e) * Dc + db * 8;
        uint32_t wo = e * 256 + ((((uint32_t)db) ^ (e & 7)) << 4);
        *(uint4*)(smem + K5_GHI + wo) = *(const uint4*)(g_kv_hi + goff);
        *(uint4*)(smem + K5_GLO + wo) = *(const uint4*)(g_kv_lo + goff);
    }

    auto FILLROW = [&](int buf, int row, float4 q) {
        float part = q.x * ksq.x + q.y * ksq.y + q.z * ksq.z + q.w * ksq.w;
        part += __shfl_xor_sync(0xFFFFFFFFu, part, 16);
        part += __shfl_xor_sync(0xFFFFFFFFu, part, 8);
        part += __shfl_xor_sync(0xFFFFFFFFu, part, 4);
        part += __shfl_xor_sync(0xFFFFFFFFu, part, 2);
        part += __shfl_xor_sync(0xFFFFFFFFu, part, 1);
        if (lane == 0) den_s[buf * 128 + row] = part;
        uint32_t base = (uint32_t)(buf * K5_ABUF);
        uint32_t wo = row * 256 + ((((uint32_t)(c4 >> 1)) ^ (row & 7)) << 4) + (c4 & 1) * 8;
        uint2 hi, lo;
        split4(q, hi, lo);
        *(uint2*)(smem + base + K5_QHI + wo) = hi;
        *(uint2*)(smem + base + K5_QLO + wo) = lo;
    };

    // ---- A fill tile0 -> buf0 ----
#pragma unroll
    for (int i = 0; i < 8; i++) {
        int row = w + 16 * i;
        float4 q = *(const float4*)(phiQ + ((size_t)(b * Lc + l0 + row) * Hc + h) * Dc + c4 * 4);
        FILLROW(0, row, q);
    }
    __syncthreads();

    const int ms = w & 3, nh = w >> 2;   // 4x4 warp grid
    const int matj = lane >> 3, rr = lane & 7;
    float acc[8][4];

    auto MMAKS = [&](int buf, int ks) {
        uint32_t abase = sb + (uint32_t)(buf * K5_ABUF);
        // A fragments: 2 m16 tiles, hi+lo
        uint32_t ah[2][4], al[2][4];
        uint32_t kbA = (uint32_t)(ks * 2 + (matj >> 1));
#pragma unroll
        for (int mi = 0; mi < 2; mi++) {
            int rowA = (ms * 2 + mi) * 16 + (matj & 1) * 8 + rr;
            uint32_t aoff = rowA * 256 + ((kbA ^ (rowA & 7)) << 4);
            ldsm_x4(ah[mi], abase + K5_QHI + aoff);
            ldsm_x4(al[mi], abase + K5_QLO + aoff);
        }
        uint32_t kbB = (uint32_t)(ks * 2 + (matj & 1));
#pragma unroll
        for (int ni = 0; ni < 2; ni++) {
            int nt = nh * 2 + ni;
            int rowB = (nt * 2 + (matj >> 1)) * 8 + rr;
            uint32_t boff = rowB * 256 + ((kbB ^ (rowB & 7)) << 4);
            uint32_t bh4[4], bl4[4];
            ldsm_x4(bh4, sb + K5_GHI + boff);
            ldsm_x4(bl4, sb + K5_GLO + boff);
#pragma unroll
            for (int mi = 0; mi < 2; mi++) {
                int a0 = (mi * 2 + ni) * 2;
                mma16816(acc[a0],     ah[mi], bh4[0], bh4[1]);
                mma16816(acc[a0],     ah[mi], bl4[0], bl4[1]);
                mma16816(acc[a0],     al[mi], bh4[0], bh4[1]);
                mma16816(acc[a0 + 1], ah[mi], bh4[2], bh4[3]);
                mma16816(acc[a0 + 1], ah[mi], bl4[2], bl4[3]);
                mma16816(acc[a0 + 1], al[mi], bh4[2], bh4[3]);
            }
        }
    };

    for (int tile = 0; tile < K5_TILES; tile++) {
        int buf = tile & 1, nbuf = buf ^ 1;
#pragma unroll
        for (int i = 0; i < 8; i++)
#pragma unroll
            for (int j = 0; j < 4; j++) acc[i][j] = 0.f;

        if (tile < K5_TILES - 1) {
#pragma unroll
            for (int g = 0; g < 8; g++) {
                int row = w + 16 * g;
                float4 qst = *(const float4*)(phiQ +
                    ((size_t)(b * Lc + l0 + (tile + 1) * 128 + row) * Hc + h) * Dc + c4 * 4);
                MMAKS(buf, g);
                FILLROW(nbuf, row, qst);
            }
        } else {
#pragma unroll
            for (int ks = 0; ks < 8; ks++) MMAKS(buf, ks);
        }

        // ---- epilogue ----
        int r_in = lane >> 2;
        int cc_in = 2 * (lane & 3);
        int lb0 = l0 + tile * 128;
#pragma unroll
        for (int mi = 0; mi < 2; mi++) {
            int row = ms * 32 + mi * 16 + r_in;
            float i0 = 1.0f / (den_s[buf * 128 + row] + EPSc);
            float i1 = 1.0f / (den_s[buf * 128 + row + 8] + EPSc);
            float* o0 = out + ((size_t)(b * Lc + lb0 + row) * Hc + h) * Dc;
            float* o1 = o0 + (size_t)8 * Hc * Dc;
#pragma unroll
            for (int ni = 0; ni < 2; ni++) {
#pragma unroll
                for (int half = 0; half < 2; half++) {
                    const float* a = acc[(mi * 2 + ni) * 2 + half];
                    int col = nh * 32 + ni * 16 + half * 8 + cc_in;
                    *(float2*)(o0 + col) = make_float2(a[0] * i0, a[1] * i0);
                    *(float2*)(o1 + col) = make_float2(a[2] * i1, a[3] * i1);
                }
            }
        }
        if (tile < K5_TILES - 1) __syncthreads();
    }
}

// ================= launcher =================
extern "C" void kernel_launch(void* const* d_in, const int* in_sizes, int n_in,
                              void* d_out, int out_size) {
    const float* Q    = (const float*)d_in[0];
    const float* K    = (const float*)d_in[1];
    const float* V    = (const float*)d_in[2];
    const float* phiQ = (const float*)d_in[3];
    const float* phiK = (const float*)d_in[4];
    float* out = (float*)d_out;

    cudaFuncSetAttribute(k4_mma, cudaFuncAttributeMaxDynamicSharedMemorySize, K4_SMEM);
    cudaFuncSetAttribute(k5_mma, cudaFuncAttributeMaxDynamicSharedMemorySize, K5_SMEM);

    k1_qpart<<<dim3(BHc, SPLITQ), 128>>>(Q);
    k2_scores<<<dim3(BHc, Lc / 256), 256>>>(K);
    k3_softmax<<<BHc, 256>>>();
    k4_mma<<<dim3(BHc, KVS), 512, K4_SMEM>>>(phiK, V);
    k4b_reduce<<<(BHc * Dc * Dc + 255) / 256, 256>>>();
    k5_mma<<<dim3(BHc, 2), 512, K5_SMEM>>>(phiQ, out);
}